// round 1
// baseline (speedup 1.0000x reference)
#include <cuda_runtime.h>

#define NB   4096
#define DIN  784
#define NH   128
#define DL   8
#define NC   16
#define CH   32
#define DOUT 10
#define NCHUNK 32
#define JT   128
#define TSTEPS 5

// ---------------- scratch (device globals; no allocation) ----------------
__device__ __align__(16) float g_z[NB*DL];
__device__ float g_sq[NB];
__device__ __align__(16) float g_hpre[NB*CH];
__device__ __align__(16) float g_hcomb[NB*CH];
__device__ __align__(16) float g_part[(size_t)NCHUNK*NB*CH];

__device__ __forceinline__ float ex2f(float x){
    float y; asm("ex2.approx.f32 %0, %1;" : "=f"(y) : "f"(x)); return y;
}
#define FMA2(d,a,b,c) asm("fma.rn.f32x2 %0, %1, %2, %3;" : "=l"(d) : "l"(a), "l"(b), "l"(c))

// ---------------- encoder: z = tanh(x@W1+b1)@W2 + b2 ----------------
__global__ __launch_bounds__(256) void enc_kernel(
    const float* __restrict__ x, const float* __restrict__ W1,
    const float* __restrict__ b1, const float* __restrict__ W2,
    const float* __restrict__ b2)
{
    __shared__ float xs[32][33];
    __shared__ __align__(16) float ws[32][NH];
    __shared__ float hs[32][NH+1];
    __shared__ float w2s[NH*DL];

    const int tid = threadIdx.x;
    const int rowBase = blockIdx.x * 32;
    const int rg = tid >> 4;     // 0..15 -> 2 rows each
    const int cg = tid & 15;     // 0..15 -> 8 cols each

    for (int t = tid; t < NH*DL; t += 256) w2s[t] = W2[t];

    float acc[2][8];
    #pragma unroll
    for (int a=0;a<2;a++)
        #pragma unroll
        for (int u=0;u<8;u++) acc[a][u]=0.f;

    for (int k0 = 0; k0 < DIN; k0 += 32) {
        for (int t = tid; t < 32*32; t += 256) {
            int r = t >> 5, k = t & 31;
            int kk = k0 + k;
            xs[r][k] = (kk < DIN) ? x[(size_t)(rowBase + r)*DIN + kk] : 0.f;
        }
        for (int t = tid; t < 32*NH; t += 256) {
            int k = t >> 7, c = t & (NH-1);
            int kk = k0 + k;
            ws[k][c] = (kk < DIN) ? W1[(size_t)kk*NH + c] : 0.f;
        }
        __syncthreads();
        #pragma unroll
        for (int kk = 0; kk < 32; kk++) {
            float x0 = xs[rg*2+0][kk];
            float x1 = xs[rg*2+1][kk];
            float4 w0 = *(const float4*)&ws[kk][cg*8];
            float4 w1 = *(const float4*)&ws[kk][cg*8+4];
            acc[0][0] = fmaf(x0, w0.x, acc[0][0]);
            acc[0][1] = fmaf(x0, w0.y, acc[0][1]);
            acc[0][2] = fmaf(x0, w0.z, acc[0][2]);
            acc[0][3] = fmaf(x0, w0.w, acc[0][3]);
            acc[0][4] = fmaf(x0, w1.x, acc[0][4]);
            acc[0][5] = fmaf(x0, w1.y, acc[0][5]);
            acc[0][6] = fmaf(x0, w1.z, acc[0][6]);
            acc[0][7] = fmaf(x0, w1.w, acc[0][7]);
            acc[1][0] = fmaf(x1, w0.x, acc[1][0]);
            acc[1][1] = fmaf(x1, w0.y, acc[1][1]);
            acc[1][2] = fmaf(x1, w0.z, acc[1][2]);
            acc[1][3] = fmaf(x1, w0.w, acc[1][3]);
            acc[1][4] = fmaf(x1, w1.x, acc[1][4]);
            acc[1][5] = fmaf(x1, w1.y, acc[1][5]);
            acc[1][6] = fmaf(x1, w1.z, acc[1][6]);
            acc[1][7] = fmaf(x1, w1.w, acc[1][7]);
        }
        __syncthreads();
    }
    #pragma unroll
    for (int a=0;a<2;a++){
        int r = rg*2+a;
        #pragma unroll
        for (int u=0;u<8;u++){
            int c = cg*8+u;
            hs[r][c] = tanhf(acc[a][u] + b1[c]);
        }
    }
    __syncthreads();
    {
        int r = tid >> 3;   // 0..31
        int o = tid & 7;    // 0..7
        float s = b2[o];
        #pragma unroll 16
        for (int k=0;k<NH;k++) s = fmaf(hs[r][k], w2s[k*DL+o], s);
        g_z[(size_t)(rowBase + r)*DL + o] = s;
    }
}

// ------------- PM field (4 steps) + h tanh-update, per row -------------
__global__ __launch_bounds__(32) void pm_h_kernel(
    const float* __restrict__ centers, const float* __restrict__ mus,
    const float* __restrict__ Wp, const float* __restrict__ bp, int useH)
{
    __shared__ float cs[NC*DL];
    __shared__ float ms[NC];
    __shared__ float wps[DL*CH];
    __shared__ float bps[CH];
    const int tid = threadIdx.x;
    for (int t = tid; t < NC*DL; t += 32) cs[t] = centers[t];
    if (tid < NC) ms[tid] = mus[tid];
    for (int t = tid; t < DL*CH; t += 32) wps[t] = Wp[t];
    bps[tid] = bp[tid];
    __syncthreads();

    const int row = blockIdx.x*32 + tid;
    float zr[DL];
    {
        float4 a = *(const float4*)&g_z[row*DL];
        float4 b = *(const float4*)&g_z[row*DL+4];
        zr[0]=a.x; zr[1]=a.y; zr[2]=a.z; zr[3]=a.w;
        zr[4]=b.x; zr[5]=b.y; zr[6]=b.z; zr[7]=b.w;
    }
    #pragma unroll
    for (int step=0; step<4; step++){
        float n = 1.f;
        float g[DL] = {0.f,0.f,0.f,0.f,0.f,0.f,0.f,0.f};
        #pragma unroll
        for (int c=0;c<NC;c++){
            float rv[DL]; float r2 = 1e-4f;
            #pragma unroll
            for (int k=0;k<DL;k++){ rv[k] = zr[k]-cs[c*DL+k]; r2 = fmaf(rv[k],rv[k],r2); }
            float rinv = rsqrtf(r2);
            float mr = ms[c]*rinv;          // mus / r
            n += mr;
            float w = mr*rinv*rinv;         // mus / r^3
            #pragma unroll
            for (int k=0;k<DL;k++) g[k] = fmaf(-w, rv[k], g[k]);
        }
        float s = 0.15f / n;                // DT*BETA / n
        #pragma unroll
        for (int k=0;k<DL;k++)
            zr[k] = fminf(fmaxf(fmaf(s, g[k], zr[k]), -3.f), 3.f);
    }
    float s2 = 0.f;
    #pragma unroll
    for (int k=0;k<DL;k++) s2 = fmaf(zr[k], zr[k], s2);
    g_sq[row] = s2;
    *(float4*)&g_z[row*DL]   = make_float4(zr[0],zr[1],zr[2],zr[3]);
    *(float4*)&g_z[row*DL+4] = make_float4(zr[4],zr[5],zr[6],zr[7]);

    float a[CH];
    #pragma unroll
    for (int c=0;c<CH;c++) a[c] = bps[c];
    #pragma unroll
    for (int k=0;k<DL;k++){
        float zk = zr[k];
        #pragma unroll
        for (int c=0;c<CH;c++) a[c] = fmaf(zk, wps[k*CH+c], a[c]);
    }
    #pragma unroll
    for (int c=0;c<CH;c+=4){
        float4 hc = make_float4(0.f,0.f,0.f,0.f);
        if (useH) hc = *(const float4*)&g_hcomb[(size_t)row*CH + c];
        float4 hv;
        hv.x = fmaf(0.9f, hc.x, 0.1f*tanhf(a[c+0]));
        hv.y = fmaf(0.9f, hc.y, 0.1f*tanhf(a[c+1]));
        hv.z = fmaf(0.9f, hc.z, 0.1f*tanhf(a[c+2]));
        hv.w = fmaf(0.9f, hc.w, 0.1f*tanhf(a[c+3]));
        *(float4*)&g_hpre[(size_t)row*CH + c] = hv;
    }
}

// ---------- lateral: part[chunk][i][:] = sum_{j in chunk} K(i,j)*h[j][:] ----------
__global__ __launch_bounds__(256,2) void lateral_kernel()
{
    __shared__ __align__(16) float4 zjs[JT*2];
    __shared__ float sqs[JT];
    __shared__ __align__(16) ulonglong2 hjs[JT*8];

    const int tid = threadIdx.x;
    const int j0 = blockIdx.y * JT;
    const int i0 = blockIdx.x * 512 + tid;
    const int i1 = i0 + 256;

    for (int t = tid; t < JT*2; t += 256) zjs[t] = ((const float4*)g_z)[j0*2 + t];
    for (int t = tid; t < JT;   t += 256) sqs[t] = g_sq[j0 + t];
    for (int t = tid; t < JT*8; t += 256) hjs[t] = ((const ulonglong2*)g_hpre)[j0*8 + t];

    float zi0[8], zi1[8];
    {
        float4 a = ((const float4*)g_z)[i0*2];
        float4 b = ((const float4*)g_z)[i0*2+1];
        zi0[0]=a.x; zi0[1]=a.y; zi0[2]=a.z; zi0[3]=a.w;
        zi0[4]=b.x; zi0[5]=b.y; zi0[6]=b.z; zi0[7]=b.w;
        a = ((const float4*)g_z)[i1*2];
        b = ((const float4*)g_z)[i1*2+1];
        zi1[0]=a.x; zi1[1]=a.y; zi1[2]=a.z; zi1[3]=a.w;
        zi1[4]=b.x; zi1[5]=b.y; zi1[6]=b.z; zi1[7]=b.w;
    }
    const float sqi0 = g_sq[i0];
    const float sqi1 = g_sq[i1];

    unsigned long long acc0[16], acc1[16];
    #pragma unroll
    for (int p=0;p<16;p++){ acc0[p]=0ULL; acc1[p]=0ULL; }

    __syncthreads();

    const float CE = -2.00374311234579f;   // -log2(e)/(2*0.6^2)
    const float CI = -0.500935778086446f;  // -log2(e)/(2*1.2^2)

    #pragma unroll 4
    for (int j=0;j<JT;j++){
        float4 zj0 = zjs[j*2];
        float4 zj1 = zjs[j*2+1];
        float sj = sqs[j];
        float d0 = zi0[0]*zj0.x;
        d0 = fmaf(zi0[1], zj0.y, d0);
        d0 = fmaf(zi0[2], zj0.z, d0);
        d0 = fmaf(zi0[3], zj0.w, d0);
        d0 = fmaf(zi0[4], zj1.x, d0);
        d0 = fmaf(zi0[5], zj1.y, d0);
        d0 = fmaf(zi0[6], zj1.z, d0);
        d0 = fmaf(zi0[7], zj1.w, d0);
        float d1 = zi1[0]*zj0.x;
        d1 = fmaf(zi1[1], zj0.y, d1);
        d1 = fmaf(zi1[2], zj0.z, d1);
        d1 = fmaf(zi1[3], zj0.w, d1);
        d1 = fmaf(zi1[4], zj1.x, d1);
        d1 = fmaf(zi1[5], zj1.y, d1);
        d1 = fmaf(zi1[6], zj1.z, d1);
        d1 = fmaf(zi1[7], zj1.w, d1);
        float dist0 = fmaxf(fmaf(-2.f, d0, sqi0 + sj), 0.f);
        float dist1 = fmaxf(fmaf(-2.f, d1, sqi1 + sj), 0.f);
        float K0 = fmaf(0.8f, ex2f(CE*dist0), -ex2f(CI*dist0));
        float K1v= fmaf(0.8f, ex2f(CE*dist1), -ex2f(CI*dist1));
        unsigned long long K0p, K1p;
        asm("mov.b64 %0, {%1, %1};" : "=l"(K0p) : "f"(K0));
        asm("mov.b64 %0, {%1, %1};" : "=l"(K1p) : "f"(K1v));
        #pragma unroll
        for (int p=0;p<8;p++){
            ulonglong2 hv = hjs[j*8+p];
            FMA2(acc0[2*p],   K0p, hv.x, acc0[2*p]);
            FMA2(acc0[2*p+1], K0p, hv.y, acc0[2*p+1]);
            FMA2(acc1[2*p],   K1p, hv.x, acc1[2*p]);
            FMA2(acc1[2*p+1], K1p, hv.y, acc1[2*p+1]);
        }
    }
    ulonglong2* o0 = (ulonglong2*)&g_part[((size_t)blockIdx.y*NB + i0)*CH];
    ulonglong2* o1 = (ulonglong2*)&g_part[((size_t)blockIdx.y*NB + i1)*CH];
    #pragma unroll
    for (int p=0;p<8;p++){
        o0[p] = make_ulonglong2(acc0[2*p], acc0[2*p+1]);
        o1[p] = make_ulonglong2(acc1[2*p], acc1[2*p+1]);
    }
}

// ---------- deterministic reduction: hcomb = hpre + 0.05 * sum(part) ----------
__global__ __launch_bounds__(256) void reduce_kernel()
{
    int idx4 = blockIdx.x*256 + threadIdx.x;   // over NB*CH/4 = 32768
    float4 s = ((const float4*)g_hpre)[idx4];
    float tx=0.f, ty=0.f, tz=0.f, tw=0.f;
    #pragma unroll
    for (int c=0;c<NCHUNK;c++){
        float4 p = ((const float4*)g_part)[(size_t)c*(NB*CH/4) + idx4];
        tx += p.x; ty += p.y; tz += p.z; tw += p.w;
    }
    s.x = fmaf(0.05f, tx, s.x);
    s.y = fmaf(0.05f, ty, s.y);
    s.z = fmaf(0.05f, tz, s.z);
    s.w = fmaf(0.05f, tw, s.w);
    ((float4*)g_hcomb)[idx4] = s;
}

// ---------------- output: y = hcomb @ Wr + br ----------------
__global__ __launch_bounds__(128) void out_kernel(const float* __restrict__ Wr,
                                                  const float* __restrict__ br,
                                                  float* __restrict__ y)
{
    __shared__ float wrs[CH*DOUT];
    __shared__ float brs[DOUT];
    int tid = threadIdx.x;
    for (int t=tid; t<CH*DOUT; t+=128) wrs[t] = Wr[t];
    if (tid < DOUT) brs[tid] = br[tid];
    __syncthreads();
    int row = blockIdx.x*128 + tid;
    float h[CH];
    #pragma unroll
    for (int c=0;c<CH;c+=4){
        float4 v = *(const float4*)&g_hcomb[(size_t)row*CH + c];
        h[c]=v.x; h[c+1]=v.y; h[c+2]=v.z; h[c+3]=v.w;
    }
    float o[DOUT];
    #pragma unroll
    for (int d=0; d<DOUT; d++) o[d] = brs[d];
    #pragma unroll
    for (int c=0;c<CH;c++){
        float hc = h[c];
        #pragma unroll
        for (int d=0; d<DOUT; d++) o[d] = fmaf(hc, wrs[c*DOUT+d], o[d]);
    }
    #pragma unroll
    for (int d=0; d<DOUT; d++) y[(size_t)row*DOUT + d] = o[d];
}

// ---------------- launch ----------------
extern "C" void kernel_launch(void* const* d_in, const int* in_sizes, int n_in,
                              void* d_out, int out_size)
{
    const float* x       = (const float*)d_in[0];
    const float* W1      = (const float*)d_in[1];
    const float* b1      = (const float*)d_in[2];
    const float* W2      = (const float*)d_in[3];
    const float* b2      = (const float*)d_in[4];
    const float* centers = (const float*)d_in[5];
    const float* mus     = (const float*)d_in[6];
    const float* Wp      = (const float*)d_in[7];
    const float* bp      = (const float*)d_in[8];
    const float* Wr      = (const float*)d_in[9];
    const float* br      = (const float*)d_in[10];
    float* y = (float*)d_out;

    enc_kernel<<<NB/32, 256>>>(x, W1, b1, W2, b2);
    for (int t = 0; t < TSTEPS; t++){
        pm_h_kernel<<<NB/32, 32>>>(centers, mus, Wp, bp, (t > 0) ? 1 : 0);
        lateral_kernel<<<dim3(NB/512, NCHUNK), 256>>>();
        reduce_kernel<<<(NB*CH/4)/256, 256>>>();
    }
    out_kernel<<<NB/128, 128>>>(Wr, br, y);
}

// round 2
// speedup vs baseline: 1.0977x; 1.0977x over previous
#include <cuda_runtime.h>

#define NB   4096
#define DIN  784
#define NH   128
#define DL   8
#define NC   16
#define CH   32
#define DOUT 10
#define NCHUNK 16
#define JT   256
#define TSTEPS 5

// ---------------- scratch (device globals; no allocation) ----------------
__device__ __align__(16) float g_z[NB*DL];
__device__ float g_sq[NB];
__device__ __align__(16) float g_hpre[NB*CH];
__device__ __align__(16) float g_hcomb[NB*CH];
__device__ __align__(16) float g_part[(size_t)NCHUNK*NB*CH];

// ---------------- precise-enough math helpers (fast-math immune) ----------
__device__ __forceinline__ float ex2f(float x){
    float y; asm("ex2.approx.f32 %0, %1;" : "=f"(y) : "f"(x)); return y;
}
__device__ __forceinline__ float rcp_acc(float x){
    float r; asm("rcp.approx.f32 %0, %1;" : "=f"(r) : "f"(x));
    return r * fmaf(-x, r, 2.0f);           // one Newton step
}
__device__ __forceinline__ float rsqrt_acc(float x){
    float r; asm("rsqrt.approx.f32 %0, %1;" : "=f"(r) : "f"(x));
    float e = x * r;
    return r * fmaf(-0.5f, e * r, 1.5f);     // one Newton step
}
__device__ __forceinline__ float tanh_acc(float x){
    float ax = fabsf(x);
    float t  = ex2f(-2.8853900817779268f * ax);   // exp(-2|x|)
    float y  = (1.0f - t) * rcp_acc(1.0f + t);
    return copysignf(y, x);
}

#define FMA2(d,a,b,c) asm("fma.rn.f32x2 %0, %1, %2, %3;" : "=l"(d) : "l"(a), "l"(b), "l"(c))
#define ADD2(d,a,b)   asm("add.rn.f32x2 %0, %1, %2;"     : "=l"(d) : "l"(a), "l"(b))
#define MUL2(d,a,b)   asm("mul.rn.f32x2 %0, %1, %2;"     : "=l"(d) : "l"(a), "l"(b))
#define PACK2(d,lo,hi) asm("mov.b64 %0, {%1, %2};" : "=l"(d) : "f"(lo), "f"(hi))
#define UNPACK2(lo,hi,s) asm("mov.b64 {%0, %1}, %2;" : "=f"(lo), "=f"(hi) : "l"(s))

// ---------------- encoder: z = tanh(x@W1+b1)@W2 + b2 ----------------
__global__ __launch_bounds__(256) void enc_kernel(
    const float* __restrict__ x, const float* __restrict__ W1,
    const float* __restrict__ b1, const float* __restrict__ W2,
    const float* __restrict__ b2)
{
    __shared__ float xs[32][33];
    __shared__ __align__(16) float ws[32][NH];
    __shared__ float hs[32][NH+1];
    __shared__ float w2s[NH*DL];

    const int tid = threadIdx.x;
    const int rowBase = blockIdx.x * 32;
    const int rg = tid >> 4;     // 0..15 -> 2 rows each
    const int cg = tid & 15;     // 0..15 -> 8 cols each

    for (int t = tid; t < NH*DL; t += 256) w2s[t] = W2[t];

    float acc[2][8];
    #pragma unroll
    for (int a=0;a<2;a++)
        #pragma unroll
        for (int u=0;u<8;u++) acc[a][u]=0.f;

    for (int k0 = 0; k0 < DIN; k0 += 32) {
        for (int t = tid; t < 32*32; t += 256) {
            int r = t >> 5, k = t & 31;
            int kk = k0 + k;
            xs[r][k] = (kk < DIN) ? x[(size_t)(rowBase + r)*DIN + kk] : 0.f;
        }
        for (int t = tid; t < 32*NH; t += 256) {
            int k = t >> 7, c = t & (NH-1);
            int kk = k0 + k;
            ws[k][c] = (kk < DIN) ? W1[(size_t)kk*NH + c] : 0.f;
        }
        __syncthreads();
        #pragma unroll
        for (int kk = 0; kk < 32; kk++) {
            float x0 = xs[rg*2+0][kk];
            float x1 = xs[rg*2+1][kk];
            float4 w0 = *(const float4*)&ws[kk][cg*8];
            float4 w1 = *(const float4*)&ws[kk][cg*8+4];
            acc[0][0] = fmaf(x0, w0.x, acc[0][0]);
            acc[0][1] = fmaf(x0, w0.y, acc[0][1]);
            acc[0][2] = fmaf(x0, w0.z, acc[0][2]);
            acc[0][3] = fmaf(x0, w0.w, acc[0][3]);
            acc[0][4] = fmaf(x0, w1.x, acc[0][4]);
            acc[0][5] = fmaf(x0, w1.y, acc[0][5]);
            acc[0][6] = fmaf(x0, w1.z, acc[0][6]);
            acc[0][7] = fmaf(x0, w1.w, acc[0][7]);
            acc[1][0] = fmaf(x1, w0.x, acc[1][0]);
            acc[1][1] = fmaf(x1, w0.y, acc[1][1]);
            acc[1][2] = fmaf(x1, w0.z, acc[1][2]);
            acc[1][3] = fmaf(x1, w0.w, acc[1][3]);
            acc[1][4] = fmaf(x1, w1.x, acc[1][4]);
            acc[1][5] = fmaf(x1, w1.y, acc[1][5]);
            acc[1][6] = fmaf(x1, w1.z, acc[1][6]);
            acc[1][7] = fmaf(x1, w1.w, acc[1][7]);
        }
        __syncthreads();
    }
    #pragma unroll
    for (int a=0;a<2;a++){
        int r = rg*2+a;
        #pragma unroll
        for (int u=0;u<8;u++){
            int c = cg*8+u;
            hs[r][c] = tanh_acc(acc[a][u] + b1[c]);
        }
    }
    __syncthreads();
    {
        int r = tid >> 3;   // 0..31
        int o = tid & 7;    // 0..7
        float s = b2[o];
        #pragma unroll 16
        for (int k=0;k<NH;k++) s = fmaf(hs[r][k], w2s[k*DL+o], s);
        g_z[(size_t)(rowBase + r)*DL + o] = s;
    }
}

// ------------- PM field (4 steps) + h tanh-update; 4 threads per row -------------
__global__ __launch_bounds__(128) void pm_h_kernel(
    const float* __restrict__ centers, const float* __restrict__ mus,
    const float* __restrict__ Wp, const float* __restrict__ bp, int useH)
{
    __shared__ float cs[NC*DL];
    __shared__ float ms[NC];
    __shared__ float wps[DL*CH];
    __shared__ float bps[CH];
    const int tid = threadIdx.x;
    if (tid < NC*DL) cs[tid] = centers[tid];
    if (tid < NC) ms[tid] = mus[tid];
    for (int t = tid; t < DL*CH; t += 128) wps[t] = Wp[t];
    if (tid < CH) bps[tid] = bp[tid];
    __syncthreads();

    const int row = blockIdx.x*32 + (tid >> 2);
    const int q   = tid & 3;           // quad lane: handles centers q*4..q*4+3

    float zr[DL];
    {
        float4 a = *(const float4*)&g_z[row*DL];
        float4 b = *(const float4*)&g_z[row*DL+4];
        zr[0]=a.x; zr[1]=a.y; zr[2]=a.z; zr[3]=a.w;
        zr[4]=b.x; zr[5]=b.y; zr[6]=b.z; zr[7]=b.w;
    }
    #pragma unroll
    for (int step=0; step<4; step++){
        float n = 0.f;
        float g[DL] = {0.f,0.f,0.f,0.f,0.f,0.f,0.f,0.f};
        #pragma unroll
        for (int cc=0;cc<4;cc++){
            int c = q*4 + cc;
            float rv[DL]; float r2 = 1e-4f;
            #pragma unroll
            for (int k=0;k<DL;k++){ rv[k] = zr[k]-cs[c*DL+k]; r2 = fmaf(rv[k],rv[k],r2); }
            float rinv = rsqrt_acc(r2);
            float mr = ms[c]*rinv;          // mus / r
            n += mr;
            float w = mr*rinv*rinv;         // mus / r^3
            #pragma unroll
            for (int k=0;k<DL;k++) g[k] = fmaf(-w, rv[k], g[k]);
        }
        // quad reduce: n and g[8]
        #pragma unroll
        for (int off=1; off<4; off<<=1){
            n += __shfl_xor_sync(0xffffffffu, n, off);
            #pragma unroll
            for (int k=0;k<DL;k++) g[k] += __shfl_xor_sync(0xffffffffu, g[k], off);
        }
        float s = 0.15f * rcp_acc(n + 1.0f);    // DT*BETA / n
        #pragma unroll
        for (int k=0;k<DL;k++)
            zr[k] = fminf(fmaxf(fmaf(s, g[k], zr[k]), -3.f), 3.f);
    }
    if (q == 0){
        float s2 = 0.f;
        #pragma unroll
        for (int k=0;k<DL;k++) s2 = fmaf(zr[k], zr[k], s2);
        g_sq[row] = s2;
        *(float4*)&g_z[row*DL]   = make_float4(zr[0],zr[1],zr[2],zr[3]);
        *(float4*)&g_z[row*DL+4] = make_float4(zr[4],zr[5],zr[6],zr[7]);
    }
    // h update: each quad lane does 8 channels
    const int c0 = q*8;
    float a8[8];
    #pragma unroll
    for (int u=0;u<8;u++) a8[u] = bps[c0+u];
    #pragma unroll
    for (int k=0;k<DL;k++){
        float zk = zr[k];
        #pragma unroll
        for (int u=0;u<8;u++) a8[u] = fmaf(zk, wps[k*CH + c0 + u], a8[u]);
    }
    float4 hc0 = make_float4(0.f,0.f,0.f,0.f), hc1 = hc0;
    if (useH){
        hc0 = *(const float4*)&g_hcomb[(size_t)row*CH + c0];
        hc1 = *(const float4*)&g_hcomb[(size_t)row*CH + c0 + 4];
    }
    float4 hv0, hv1;
    hv0.x = fmaf(0.9f, hc0.x, 0.1f*tanh_acc(a8[0]));
    hv0.y = fmaf(0.9f, hc0.y, 0.1f*tanh_acc(a8[1]));
    hv0.z = fmaf(0.9f, hc0.z, 0.1f*tanh_acc(a8[2]));
    hv0.w = fmaf(0.9f, hc0.w, 0.1f*tanh_acc(a8[3]));
    hv1.x = fmaf(0.9f, hc1.x, 0.1f*tanh_acc(a8[4]));
    hv1.y = fmaf(0.9f, hc1.y, 0.1f*tanh_acc(a8[5]));
    hv1.z = fmaf(0.9f, hc1.z, 0.1f*tanh_acc(a8[6]));
    hv1.w = fmaf(0.9f, hc1.w, 0.1f*tanh_acc(a8[7]));
    *(float4*)&g_hpre[(size_t)row*CH + c0]     = hv0;
    *(float4*)&g_hpre[(size_t)row*CH + c0 + 4] = hv1;
}

// ---------- lateral: part[chunk][i][:] = sum_{j in chunk} K(i,j)*h[j][:] ----------
__global__ __launch_bounds__(256,2) void lateral_kernel()
{
    __shared__ __align__(16) unsigned long long zjd[JT*8];  // duplicated zj components
    __shared__ __align__(16) unsigned long long sjd[JT];    // duplicated -0.5*sq_j
    __shared__ __align__(16) ulonglong2 hjs[JT*8];          // h rows (f32x2 pairs)

    const int tid = threadIdx.x;
    const int j0 = blockIdx.y * JT;
    const int i0 = blockIdx.x * 512 + tid;
    const int i1 = i0 + 256;

    for (int t = tid; t < JT*8; t += 256){
        float v = g_z[(size_t)j0*8 + t];
        unsigned long long p; PACK2(p, v, v);
        zjd[t] = p;
    }
    for (int t = tid; t < JT; t += 256){
        float v = -0.5f * g_sq[j0 + t];
        unsigned long long p; PACK2(p, v, v);
        sjd[t] = p;
    }
    for (int t = tid; t < JT*8; t += 256) hjs[t] = ((const ulonglong2*)g_hpre)[(size_t)j0*8 + t];

    // packed (zi0[k], zi1[k])
    unsigned long long zp[8];
    {
        float4 a = ((const float4*)g_z)[(size_t)i0*2];
        float4 b = ((const float4*)g_z)[(size_t)i0*2+1];
        float4 c = ((const float4*)g_z)[(size_t)i1*2];
        float4 d = ((const float4*)g_z)[(size_t)i1*2+1];
        PACK2(zp[0], a.x, c.x); PACK2(zp[1], a.y, c.y);
        PACK2(zp[2], a.z, c.z); PACK2(zp[3], a.w, c.w);
        PACK2(zp[4], b.x, d.x); PACK2(zp[5], b.y, d.y);
        PACK2(zp[6], b.z, d.z); PACK2(zp[7], b.w, d.w);
    }
    unsigned long long nsqp;   // (-0.5*sq_i0, -0.5*sq_i1)
    {
        float s0 = -0.5f * g_sq[i0];
        float s1 = -0.5f * g_sq[i1];
        PACK2(nsqp, s0, s1);
    }
    unsigned long long m2ci;   // (-2*CI, -2*CI), CI = -log2e/(2*1.2^2)
    {
        const float c = 1.0018715561728892f;
        PACK2(m2ci, c, c);
    }

    unsigned long long acc0[16], acc1[16];
    #pragma unroll
    for (int p=0;p<16;p++){ acc0[p]=0ULL; acc1[p]=0ULL; }

    __syncthreads();

    #pragma unroll 4
    for (int j=0;j<JT;j++){
        // dd = (zi . zj) - 0.5*si - 0.5*sj   (packed over the two i rows)
        unsigned long long dd;
        ADD2(dd, sjd[j], nsqp);
        #pragma unroll
        for (int k=0;k<8;k++) FMA2(dd, zp[k], zjd[j*8+k], dd);
        // earg = CI * dist2 = (-2*CI) * dd ; dist2>=0 -> earg<=0
        unsigned long long eargp;
        MUL2(eargp, dd, m2ci);
        float e0, e1; UNPACK2(e0, e1, eargp);
        e0 = fminf(e0, 0.f); e1 = fminf(e1, 0.f);
        float eI0 = ex2f(e0), eI1 = ex2f(e1);        // exp(-d2/(2*1.44))
        float p0 = eI0*eI0,  p1 = eI1*eI1;
        float K0 = fmaf(0.8f, p0*p0, -eI0);          // E_E = E_I^4 exactly (sigma ratio = 2)
        float K1 = fmaf(0.8f, p1*p1, -eI1);
        unsigned long long K0p, K1p;
        PACK2(K0p, K0, K0);
        PACK2(K1p, K1, K1);
        #pragma unroll
        for (int p=0;p<8;p++){
            ulonglong2 hv = hjs[j*8+p];
            FMA2(acc0[2*p],   K0p, hv.x, acc0[2*p]);
            FMA2(acc0[2*p+1], K0p, hv.y, acc0[2*p+1]);
            FMA2(acc1[2*p],   K1p, hv.x, acc1[2*p]);
            FMA2(acc1[2*p+1], K1p, hv.y, acc1[2*p+1]);
        }
    }
    ulonglong2* o0 = (ulonglong2*)&g_part[((size_t)blockIdx.y*NB + i0)*CH];
    ulonglong2* o1 = (ulonglong2*)&g_part[((size_t)blockIdx.y*NB + i1)*CH];
    #pragma unroll
    for (int p=0;p<8;p++){
        o0[p] = make_ulonglong2(acc0[2*p], acc0[2*p+1]);
        o1[p] = make_ulonglong2(acc1[2*p], acc1[2*p+1]);
    }
}

// ---------- deterministic reduction: hcomb = hpre + 0.05 * sum(part) ----------
__global__ __launch_bounds__(256) void reduce_kernel()
{
    int idx4 = blockIdx.x*256 + threadIdx.x;   // over NB*CH/4 = 32768
    float4 s = ((const float4*)g_hpre)[idx4];
    float tx=0.f, ty=0.f, tz=0.f, tw=0.f;
    #pragma unroll
    for (int c=0;c<NCHUNK;c++){
        float4 p = ((const float4*)g_part)[(size_t)c*(NB*CH/4) + idx4];
        tx += p.x; ty += p.y; tz += p.z; tw += p.w;
    }
    s.x = fmaf(0.05f, tx, s.x);
    s.y = fmaf(0.05f, ty, s.y);
    s.z = fmaf(0.05f, tz, s.z);
    s.w = fmaf(0.05f, tw, s.w);
    ((float4*)g_hcomb)[idx4] = s;
}

// ---------------- output: y = hcomb @ Wr + br ----------------
__global__ __launch_bounds__(128) void out_kernel(const float* __restrict__ Wr,
                                                  const float* __restrict__ br,
                                                  float* __restrict__ y)
{
    __shared__ float wrs[CH*DOUT];
    __shared__ float brs[DOUT];
    int tid = threadIdx.x;
    for (int t=tid; t<CH*DOUT; t+=128) wrs[t] = Wr[t];
    if (tid < DOUT) brs[tid] = br[tid];
    __syncthreads();
    int row = blockIdx.x*128 + tid;
    float h[CH];
    #pragma unroll
    for (int c=0;c<CH;c+=4){
        float4 v = *(const float4*)&g_hcomb[(size_t)row*CH + c];
        h[c]=v.x; h[c+1]=v.y; h[c+2]=v.z; h[c+3]=v.w;
    }
    float o[DOUT];
    #pragma unroll
    for (int d=0; d<DOUT; d++) o[d] = brs[d];
    #pragma unroll
    for (int c=0;c<CH;c++){
        float hc = h[c];
        #pragma unroll
        for (int d=0; d<DOUT; d++) o[d] = fmaf(hc, wrs[c*DOUT+d], o[d]);
    }
    #pragma unroll
    for (int d=0; d<DOUT; d++) y[(size_t)row*DOUT + d] = o[d];
}

// ---------------- launch ----------------
extern "C" void kernel_launch(void* const* d_in, const int* in_sizes, int n_in,
                              void* d_out, int out_size)
{
    const float* x       = (const float*)d_in[0];
    const float* W1      = (const float*)d_in[1];
    const float* b1      = (const float*)d_in[2];
    const float* W2      = (const float*)d_in[3];
    const float* b2      = (const float*)d_in[4];
    const float* centers = (const float*)d_in[5];
    const float* mus     = (const float*)d_in[6];
    const float* Wp      = (const float*)d_in[7];
    const float* bp      = (const float*)d_in[8];
    const float* Wr      = (const float*)d_in[9];
    const float* br      = (const float*)d_in[10];
    float* y = (float*)d_out;

    enc_kernel<<<NB/32, 256>>>(x, W1, b1, W2, b2);
    for (int t = 0; t < TSTEPS; t++){
        pm_h_kernel<<<NB/32, 128>>>(centers, mus, Wp, bp, (t > 0) ? 1 : 0);
        lateral_kernel<<<dim3(NB/512, NCHUNK), 256>>>();
        reduce_kernel<<<(NB*CH/4)/256, 256>>>();
    }
    out_kernel<<<NB/128, 128>>>(Wr, br, y);
}

// round 3
// speedup vs baseline: 1.1212x; 1.0214x over previous
#include <cuda_runtime.h>

#define NB   4096
#define DIN  784
#define NH   128
#define DL   8
#define NC   16
#define CH   32
#define DOUT 10
#define NCHUNK 32
#define JT   128
#define TSTEPS 5

// ---------------- scratch (device globals; no allocation) ----------------
__device__ __align__(16) float g_z[NB*DL];
__device__ float g_sq[NB];
__device__ __align__(16) float g_hpre[NB*CH];
__device__ __align__(16) float g_part[(size_t)NCHUNK*NB*CH];

// ---------------- precise-enough math helpers (fast-math immune) ----------
__device__ __forceinline__ float ex2f(float x){
    float y; asm("ex2.approx.f32 %0, %1;" : "=f"(y) : "f"(x)); return y;
}
__device__ __forceinline__ float rcp_acc(float x){
    float r; asm("rcp.approx.f32 %0, %1;" : "=f"(r) : "f"(x));
    return r * fmaf(-x, r, 2.0f);           // one Newton step
}
__device__ __forceinline__ float rsqrt_acc(float x){
    float r; asm("rsqrt.approx.f32 %0, %1;" : "=f"(r) : "f"(x));
    float e = x * r;
    return r * fmaf(-0.5f, e * r, 1.5f);     // one Newton step
}
__device__ __forceinline__ float tanh_acc(float x){
    float ax = fabsf(x);
    float t  = ex2f(-2.8853900817779268f * ax);   // exp(-2|x|)
    float y  = (1.0f - t) * rcp_acc(1.0f + t);
    return copysignf(y, x);
}

#define FMA2(d,a,b,c) asm("fma.rn.f32x2 %0, %1, %2, %3;" : "=l"(d) : "l"(a), "l"(b), "l"(c))
#define ADD2(d,a,b)   asm("add.rn.f32x2 %0, %1, %2;"     : "=l"(d) : "l"(a), "l"(b))
#define MUL2(d,a,b)   asm("mul.rn.f32x2 %0, %1, %2;"     : "=l"(d) : "l"(a), "l"(b))
#define PACK2(d,lo,hi) asm("mov.b64 %0, {%1, %2};" : "=l"(d) : "f"(lo), "f"(hi))
#define UNPACK2(lo,hi,s) asm("mov.b64 {%0, %1}, %2;" : "=f"(lo), "=f"(hi) : "l"(s))

// CI = -log2(e)/(2*1.2^2)
#define CI_F   (-0.50093577808644655f)
#define M2CI_F ( 1.0018715561728931f)   // -2*CI

// ---------------- encoder: z = tanh(x@W1+b1)@W2 + b2 ----------------
__global__ __launch_bounds__(256) void enc_kernel(
    const float* __restrict__ x, const float* __restrict__ W1,
    const float* __restrict__ b1, const float* __restrict__ W2,
    const float* __restrict__ b2)
{
    __shared__ float xs[32][33];
    __shared__ __align__(16) float ws[32][NH];
    __shared__ float hs[32][NH+1];
    __shared__ float w2s[NH*DL];

    const int tid = threadIdx.x;
    const int rowBase = blockIdx.x * 32;
    const int rg = tid >> 4;     // 0..15 -> 2 rows each
    const int cg = tid & 15;     // 0..15 -> 8 cols each

    for (int t = tid; t < NH*DL; t += 256) w2s[t] = W2[t];

    float acc[2][8];
    #pragma unroll
    for (int a=0;a<2;a++)
        #pragma unroll
        for (int u=0;u<8;u++) acc[a][u]=0.f;

    for (int k0 = 0; k0 < DIN; k0 += 32) {
        for (int t = tid; t < 32*32; t += 256) {
            int r = t >> 5, k = t & 31;
            int kk = k0 + k;
            xs[r][k] = (kk < DIN) ? x[(size_t)(rowBase + r)*DIN + kk] : 0.f;
        }
        for (int t = tid; t < 32*NH; t += 256) {
            int k = t >> 7, c = t & (NH-1);
            int kk = k0 + k;
            ws[k][c] = (kk < DIN) ? W1[(size_t)kk*NH + c] : 0.f;
        }
        __syncthreads();
        #pragma unroll
        for (int kk = 0; kk < 32; kk++) {
            float x0 = xs[rg*2+0][kk];
            float x1 = xs[rg*2+1][kk];
            float4 w0 = *(const float4*)&ws[kk][cg*8];
            float4 w1 = *(const float4*)&ws[kk][cg*8+4];
            acc[0][0] = fmaf(x0, w0.x, acc[0][0]);
            acc[0][1] = fmaf(x0, w0.y, acc[0][1]);
            acc[0][2] = fmaf(x0, w0.z, acc[0][2]);
            acc[0][3] = fmaf(x0, w0.w, acc[0][3]);
            acc[0][4] = fmaf(x0, w1.x, acc[0][4]);
            acc[0][5] = fmaf(x0, w1.y, acc[0][5]);
            acc[0][6] = fmaf(x0, w1.z, acc[0][6]);
            acc[0][7] = fmaf(x0, w1.w, acc[0][7]);
            acc[1][0] = fmaf(x1, w0.x, acc[1][0]);
            acc[1][1] = fmaf(x1, w0.y, acc[1][1]);
            acc[1][2] = fmaf(x1, w0.z, acc[1][2]);
            acc[1][3] = fmaf(x1, w0.w, acc[1][3]);
            acc[1][4] = fmaf(x1, w1.x, acc[1][4]);
            acc[1][5] = fmaf(x1, w1.y, acc[1][5]);
            acc[1][6] = fmaf(x1, w1.z, acc[1][6]);
            acc[1][7] = fmaf(x1, w1.w, acc[1][7]);
        }
        __syncthreads();
    }
    #pragma unroll
    for (int a=0;a<2;a++){
        int r = rg*2+a;
        #pragma unroll
        for (int u=0;u<8;u++){
            int c = cg*8+u;
            hs[r][c] = tanh_acc(acc[a][u] + b1[c]);
        }
    }
    __syncthreads();
    {
        int r = tid >> 3;   // 0..31
        int o = tid & 7;    // 0..7
        float s = b2[o];
        #pragma unroll 16
        for (int k=0;k<NH;k++) s = fmaf(hs[r][k], w2s[k*DL+o], s);
        g_z[(size_t)(rowBase + r)*DL + o] = s;
    }
}

// ---- shared device routine: pm field (4 steps) with quad-parallel centers ----
__device__ __forceinline__ void pm_quad(float zr[DL], const float* cs,
                                        const float* ms, int q)
{
    #pragma unroll
    for (int step=0; step<4; step++){
        float n = 0.f;
        float g[DL] = {0.f,0.f,0.f,0.f,0.f,0.f,0.f,0.f};
        #pragma unroll
        for (int cc=0;cc<4;cc++){
            int c = q*4 + cc;
            float rv[DL]; float r2 = 1e-4f;
            #pragma unroll
            for (int k=0;k<DL;k++){ rv[k] = zr[k]-cs[c*DL+k]; r2 = fmaf(rv[k],rv[k],r2); }
            float rinv = rsqrt_acc(r2);
            float mr = ms[c]*rinv;          // mus / r
            n += mr;
            float w = mr*rinv*rinv;         // mus / r^3
            #pragma unroll
            for (int k=0;k<DL;k++) g[k] = fmaf(-w, rv[k], g[k]);
        }
        #pragma unroll
        for (int off=1; off<4; off<<=1){
            n += __shfl_xor_sync(0xffffffffu, n, off);
            #pragma unroll
            for (int k=0;k<DL;k++) g[k] += __shfl_xor_sync(0xffffffffu, g[k], off);
        }
        float s = 0.15f * rcp_acc(n + 1.0f);    // DT*BETA / n
        #pragma unroll
        for (int k=0;k<DL;k++)
            zr[k] = fminf(fmaxf(fmaf(s, g[k], zr[k]), -3.f), 3.f);
    }
}

// ---- shared device routine: hpre = 0.9*hc + 0.1*tanh(z@Wp+bp) for 8 channels ----
__device__ __forceinline__ void h_update_store(const float zr[DL], const float* wps,
                                               const float* bps, int row, int c0,
                                               float4 hc0, float4 hc1)
{
    float a8[8];
    #pragma unroll
    for (int u=0;u<8;u++) a8[u] = bps[c0+u];
    #pragma unroll
    for (int k=0;k<DL;k++){
        float zk = zr[k];
        #pragma unroll
        for (int u=0;u<8;u++) a8[u] = fmaf(zk, wps[k*CH + c0 + u], a8[u]);
    }
    float4 hv0, hv1;
    hv0.x = fmaf(0.9f, hc0.x, 0.1f*tanh_acc(a8[0]));
    hv0.y = fmaf(0.9f, hc0.y, 0.1f*tanh_acc(a8[1]));
    hv0.z = fmaf(0.9f, hc0.z, 0.1f*tanh_acc(a8[2]));
    hv0.w = fmaf(0.9f, hc0.w, 0.1f*tanh_acc(a8[3]));
    hv1.x = fmaf(0.9f, hc1.x, 0.1f*tanh_acc(a8[4]));
    hv1.y = fmaf(0.9f, hc1.y, 0.1f*tanh_acc(a8[5]));
    hv1.z = fmaf(0.9f, hc1.z, 0.1f*tanh_acc(a8[6]));
    hv1.w = fmaf(0.9f, hc1.w, 0.1f*tanh_acc(a8[7]));
    *(float4*)&g_hpre[(size_t)row*CH + c0]     = hv0;
    *(float4*)&g_hpre[(size_t)row*CH + c0 + 4] = hv1;
}

// ------------- prep: z=pm(z0), sq, hpre (h starts at 0); 4 threads/row -------------
__global__ __launch_bounds__(128) void prep_kernel(
    const float* __restrict__ centers, const float* __restrict__ mus,
    const float* __restrict__ Wp, const float* __restrict__ bp)
{
    __shared__ float cs[NC*DL];
    __shared__ float ms[NC];
    __shared__ float wps[DL*CH];
    __shared__ float bps[CH];
    const int tid = threadIdx.x;
    if (tid < NC*DL) cs[tid] = centers[tid];
    if (tid < NC) ms[tid] = mus[tid];
    for (int t = tid; t < DL*CH; t += 128) wps[t] = Wp[t];
    if (tid < CH) bps[tid] = bp[tid];
    __syncthreads();

    const int row = blockIdx.x*32 + (tid >> 2);
    const int q   = tid & 3;

    float zr[DL];
    {
        float4 a = *(const float4*)&g_z[row*DL];
        float4 b = *(const float4*)&g_z[row*DL+4];
        zr[0]=a.x; zr[1]=a.y; zr[2]=a.z; zr[3]=a.w;
        zr[4]=b.x; zr[5]=b.y; zr[6]=b.z; zr[7]=b.w;
    }
    pm_quad(zr, cs, ms, q);
    if (q == 0){
        float s2 = 0.f;
        #pragma unroll
        for (int k=0;k<DL;k++) s2 = fmaf(zr[k], zr[k], s2);
        g_sq[row] = s2;
        *(float4*)&g_z[row*DL]   = make_float4(zr[0],zr[1],zr[2],zr[3]);
        *(float4*)&g_z[row*DL+4] = make_float4(zr[4],zr[5],zr[6],zr[7]);
    }
    float4 z4 = make_float4(0.f,0.f,0.f,0.f);
    h_update_store(zr, wps, bps, row, q*8, z4, z4);
}

// ---------- lateral: part[chunk][i][:] = sum_{j in chunk} K(i,j)*h[j][:] ----------
__global__ __launch_bounds__(256,2) void lateral_kernel()
{
    __shared__ __align__(16) unsigned long long zjd[JT*8];  // dup (-2CI)*zj
    __shared__ __align__(16) unsigned long long sjd[JT];    // dup CI*sq_j
    __shared__ __align__(16) ulonglong2 hjs[JT*8];          // h rows (f32x2 pairs)

    const int tid = threadIdx.x;
    const int j0 = blockIdx.y * JT;
    const int i0 = blockIdx.x * 512 + tid;
    const int i1 = i0 + 256;

    for (int t = tid; t < JT*8; t += 256){
        float v = M2CI_F * g_z[(size_t)j0*8 + t];
        unsigned long long p; PACK2(p, v, v);
        zjd[t] = p;
    }
    for (int t = tid; t < JT; t += 256){
        float v = CI_F * g_sq[j0 + t];
        unsigned long long p; PACK2(p, v, v);
        sjd[t] = p;
    }
    for (int t = tid; t < JT*8; t += 256) hjs[t] = ((const ulonglong2*)g_hpre)[(size_t)j0*8 + t];

    // packed (zi0[k], zi1[k])
    unsigned long long zp[8];
    {
        float4 a = ((const float4*)g_z)[(size_t)i0*2];
        float4 b = ((const float4*)g_z)[(size_t)i0*2+1];
        float4 c = ((const float4*)g_z)[(size_t)i1*2];
        float4 d = ((const float4*)g_z)[(size_t)i1*2+1];
        PACK2(zp[0], a.x, c.x); PACK2(zp[1], a.y, c.y);
        PACK2(zp[2], a.z, c.z); PACK2(zp[3], a.w, c.w);
        PACK2(zp[4], b.x, d.x); PACK2(zp[5], b.y, d.y);
        PACK2(zp[6], b.z, d.z); PACK2(zp[7], b.w, d.w);
    }
    unsigned long long nsqp;   // (CI*sq_i0, CI*sq_i1)
    {
        float s0 = CI_F * g_sq[i0];
        float s1 = CI_F * g_sq[i1];
        PACK2(nsqp, s0, s1);
    }
    unsigned long long four_p;
    PACK2(four_p, 4.0f, 4.0f);

    unsigned long long acc0[16], acc1[16];
    #pragma unroll
    for (int p=0;p<16;p++){ acc0[p]=0ULL; acc1[p]=0ULL; }

    __syncthreads();

    #pragma unroll 4
    for (int j=0;j<JT;j++){
        // earg = CI*(si + sj - 2*dot) packed over the two i rows
        unsigned long long ea;
        ADD2(ea, sjd[j], nsqp);
        #pragma unroll
        for (int k=0;k<8;k++) FMA2(ea, zp[k], zjd[j*8+k], ea);
        unsigned long long e4;
        MUL2(e4, ea, four_p);                    // E_E exponent = 4*earg
        float x0, x1, y0, y1;
        UNPACK2(x0, x1, ea);
        UNPACK2(y0, y1, e4);
        float ei0 = ex2f(x0), ei1 = ex2f(x1);    // E_I
        float ee0 = ex2f(y0), ee1 = ex2f(y1);    // E_E = E_I^4
        float K0 = fmaf(0.8f, ee0, -ei0);
        float K1 = fmaf(0.8f, ee1, -ei1);
        unsigned long long K0p, K1p;
        PACK2(K0p, K0, K0);
        PACK2(K1p, K1, K1);
        #pragma unroll
        for (int p=0;p<8;p++){
            ulonglong2 hv = hjs[j*8+p];
            FMA2(acc0[2*p],   K0p, hv.x, acc0[2*p]);
            FMA2(acc0[2*p+1], K0p, hv.y, acc0[2*p+1]);
            FMA2(acc1[2*p],   K1p, hv.x, acc1[2*p]);
            FMA2(acc1[2*p+1], K1p, hv.y, acc1[2*p+1]);
        }
    }
    ulonglong2* o0 = (ulonglong2*)&g_part[((size_t)blockIdx.y*NB + i0)*CH];
    ulonglong2* o1 = (ulonglong2*)&g_part[((size_t)blockIdx.y*NB + i1)*CH];
    #pragma unroll
    for (int p=0;p<8;p++){
        o0[p] = make_ulonglong2(acc0[2*p], acc0[2*p+1]);
        o1[p] = make_ulonglong2(acc1[2*p], acc1[2*p+1]);
    }
}

// ------- fused: hcomb = hpre + 0.05*sum(part); z = pm(z); hpre = 0.9*hcomb + ... -------
__global__ __launch_bounds__(128) void fused_kernel(
    const float* __restrict__ centers, const float* __restrict__ mus,
    const float* __restrict__ Wp, const float* __restrict__ bp)
{
    __shared__ float cs[NC*DL];
    __shared__ float ms[NC];
    __shared__ float wps[DL*CH];
    __shared__ float bps[CH];
    const int tid = threadIdx.x;
    if (tid < NC*DL) cs[tid] = centers[tid];
    if (tid < NC) ms[tid] = mus[tid];
    for (int t = tid; t < DL*CH; t += 128) wps[t] = Wp[t];
    if (tid < CH) bps[tid] = bp[tid];
    __syncthreads();

    const int row = blockIdx.x*32 + (tid >> 2);
    const int q   = tid & 3;
    const int c0  = q*8;

    // reduce partials for this row's 8 channels
    float t0x=0.f,t0y=0.f,t0z=0.f,t0w=0.f, t1x=0.f,t1y=0.f,t1z=0.f,t1w=0.f;
    #pragma unroll
    for (int c=0;c<NCHUNK;c++){
        const float* base = &g_part[((size_t)c*NB + row)*CH + c0];
        float4 p0 = *(const float4*)base;
        float4 p1 = *(const float4*)(base+4);
        t0x+=p0.x; t0y+=p0.y; t0z+=p0.z; t0w+=p0.w;
        t1x+=p1.x; t1y+=p1.y; t1z+=p1.z; t1w+=p1.w;
    }
    float4 h0 = *(const float4*)&g_hpre[(size_t)row*CH + c0];
    float4 h1 = *(const float4*)&g_hpre[(size_t)row*CH + c0 + 4];
    float4 hc0, hc1;
    hc0.x = fmaf(0.05f, t0x, h0.x); hc0.y = fmaf(0.05f, t0y, h0.y);
    hc0.z = fmaf(0.05f, t0z, h0.z); hc0.w = fmaf(0.05f, t0w, h0.w);
    hc1.x = fmaf(0.05f, t1x, h1.x); hc1.y = fmaf(0.05f, t1y, h1.y);
    hc1.z = fmaf(0.05f, t1z, h1.z); hc1.w = fmaf(0.05f, t1w, h1.w);

    // pm update of z
    float zr[DL];
    {
        float4 a = *(const float4*)&g_z[row*DL];
        float4 b = *(const float4*)&g_z[row*DL+4];
        zr[0]=a.x; zr[1]=a.y; zr[2]=a.z; zr[3]=a.w;
        zr[4]=b.x; zr[5]=b.y; zr[6]=b.z; zr[7]=b.w;
    }
    pm_quad(zr, cs, ms, q);
    if (q == 0){
        float s2 = 0.f;
        #pragma unroll
        for (int k=0;k<DL;k++) s2 = fmaf(zr[k], zr[k], s2);
        g_sq[row] = s2;
        *(float4*)&g_z[row*DL]   = make_float4(zr[0],zr[1],zr[2],zr[3]);
        *(float4*)&g_z[row*DL+4] = make_float4(zr[4],zr[5],zr[6],zr[7]);
    }
    h_update_store(zr, wps, bps, row, c0, hc0, hc1);
}

// ------- final: hcomb = hpre + 0.05*sum(part); y = hcomb @ Wr + br -------
__global__ __launch_bounds__(128) void final_kernel(
    const float* __restrict__ Wr, const float* __restrict__ br,
    float* __restrict__ y)
{
    __shared__ float wrs[CH*DOUT];
    __shared__ float brs[DOUT];
    const int tid = threadIdx.x;
    for (int t=tid; t<CH*DOUT; t+=128) wrs[t] = Wr[t];
    if (tid < DOUT) brs[tid] = br[tid];
    __syncthreads();

    const int row = blockIdx.x*32 + (tid >> 2);
    const int q   = tid & 3;
    const int c0  = q*8;

    float t0x=0.f,t0y=0.f,t0z=0.f,t0w=0.f, t1x=0.f,t1y=0.f,t1z=0.f,t1w=0.f;
    #pragma unroll
    for (int c=0;c<NCHUNK;c++){
        const float* base = &g_part[((size_t)c*NB + row)*CH + c0];
        float4 p0 = *(const float4*)base;
        float4 p1 = *(const float4*)(base+4);
        t0x+=p0.x; t0y+=p0.y; t0z+=p0.z; t0w+=p0.w;
        t1x+=p1.x; t1y+=p1.y; t1z+=p1.z; t1w+=p1.w;
    }
    float4 h0 = *(const float4*)&g_hpre[(size_t)row*CH + c0];
    float4 h1 = *(const float4*)&g_hpre[(size_t)row*CH + c0 + 4];
    float hc[8];
    hc[0] = fmaf(0.05f, t0x, h0.x); hc[1] = fmaf(0.05f, t0y, h0.y);
    hc[2] = fmaf(0.05f, t0z, h0.z); hc[3] = fmaf(0.05f, t0w, h0.w);
    hc[4] = fmaf(0.05f, t1x, h1.x); hc[5] = fmaf(0.05f, t1y, h1.y);
    hc[6] = fmaf(0.05f, t1z, h1.z); hc[7] = fmaf(0.05f, t1w, h1.w);

    float o[DOUT];
    #pragma unroll
    for (int d=0; d<DOUT; d++) o[d] = 0.f;
    #pragma unroll
    for (int u=0;u<8;u++){
        float hcu = hc[u];
        #pragma unroll
        for (int d=0; d<DOUT; d++) o[d] = fmaf(hcu, wrs[(c0+u)*DOUT+d], o[d]);
    }
    #pragma unroll
    for (int off=1; off<4; off<<=1){
        #pragma unroll
        for (int d=0; d<DOUT; d++) o[d] += __shfl_xor_sync(0xffffffffu, o[d], off);
    }
    if (q == 0){
        #pragma unroll
        for (int d=0; d<DOUT; d++) y[(size_t)row*DOUT + d] = o[d] + brs[d];
    }
}

// ---------------- launch ----------------
extern "C" void kernel_launch(void* const* d_in, const int* in_sizes, int n_in,
                              void* d_out, int out_size)
{
    const float* x       = (const float*)d_in[0];
    const float* W1      = (const float*)d_in[1];
    const float* b1      = (const float*)d_in[2];
    const float* W2      = (const float*)d_in[3];
    const float* b2      = (const float*)d_in[4];
    const float* centers = (const float*)d_in[5];
    const float* mus     = (const float*)d_in[6];
    const float* Wp      = (const float*)d_in[7];
    const float* bp      = (const float*)d_in[8];
    const float* Wr      = (const float*)d_in[9];
    const float* br      = (const float*)d_in[10];
    float* y = (float*)d_out;

    enc_kernel<<<NB/32, 256>>>(x, W1, b1, W2, b2);
    prep_kernel<<<NB/32, 128>>>(centers, mus, Wp, bp);
    for (int t = 1; t <= TSTEPS; t++){
        lateral_kernel<<<dim3(NB/512, NCHUNK), 256>>>();
        if (t < TSTEPS)
            fused_kernel<<<NB/32, 128>>>(centers, mus, Wp, bp);
    }
    final_kernel<<<NB/32, 128>>>(Wr, br, y);
}

// round 5
// speedup vs baseline: 1.6874x; 1.5050x over previous
#include <cuda_runtime.h>
#include <cuda_bf16.h>
#include <cstdint>

#define NB   4096
#define DIN  784
#define NH   128
#define DL   8
#define NC   16
#define CH   32
#define DOUT 10
#define NCHUNK 8
#define TSTEPS 5

// lateral MMA tiling
#define ITILE 128
#define KC    64          // j per chunk
#define NJS   8           // j splits
#define JRANGE (NB/NJS)   // 512 j per CTA
#define NCH   (JRANGE/KC) // 8 chunks

// ---------------- scratch (device globals; no allocation) ----------------
__device__ __align__(16) float g_z[NB*DL];
__device__ float g_sq[NB];
__device__ __align__(16) float g_hpre[NB*CH];
__device__ __align__(16) char  g_hT[NB*CH*2];     // bf16, transposed+SW128 per 64-j chunk
__device__ __align__(16) float g_part[(size_t)NCHUNK*NB*CH];

// ---------------- math helpers (fast-math immune) ----------
__device__ __forceinline__ float ex2f(float x){
    float y; asm("ex2.approx.f32 %0, %1;" : "=f"(y) : "f"(x)); return y;
}
__device__ __forceinline__ float rcp_acc(float x){
    float r; asm("rcp.approx.f32 %0, %1;" : "=f"(r) : "f"(x));
    return r * fmaf(-x, r, 2.0f);
}
__device__ __forceinline__ float rsqrt_acc(float x){
    float r; asm("rsqrt.approx.f32 %0, %1;" : "=f"(r) : "f"(x));
    float e = x * r;
    return r * fmaf(-0.5f, e * r, 1.5f);
}
__device__ __forceinline__ float tanh_acc(float x){
    float ax = fabsf(x);
    float t  = ex2f(-2.8853900817779268f * ax);
    float y  = (1.0f - t) * rcp_acc(1.0f + t);
    return copysignf(y, x);
}

#define FMA2(d,a,b,c) asm("fma.rn.f32x2 %0, %1, %2, %3;" : "=l"(d) : "l"(a), "l"(b), "l"(c))
#define ADD2(d,a,b)   asm("add.rn.f32x2 %0, %1, %2;"     : "=l"(d) : "l"(a), "l"(b))
#define PACK2(d,lo,hi) asm("mov.b64 %0, {%1, %2};" : "=l"(d) : "f"(lo), "f"(hi))
#define UNPACK2(lo,hi,s) asm("mov.b64 {%0, %1}, %2;" : "=f"(lo), "=f"(hi) : "l"(s))

// CI = -log2(e)/(2*1.2^2)
#define CI_F   (-0.50093577808644655f)
#define M2CI_F ( 1.0018715561728931f)   // -2*CI

#define SWZ128(b) ((b) ^ (((b) >> 3) & 0x70))

__device__ __forceinline__ uint32_t smem_u32(const void* p){
    uint32_t a;
    asm("{ .reg .u64 t; cvta.to.shared.u64 t, %1; cvt.u32.u64 %0, t; }" : "=r"(a) : "l"(p));
    return a;
}

// ---------------- warp-level MMA plumbing (sm_80+ path) ----------------
#define LDSM_X4(r0,r1,r2,r3,addr) \
    asm volatile("ldmatrix.sync.aligned.m8n8.x4.shared.b16 {%0,%1,%2,%3}, [%4];" \
        : "=r"(r0),"=r"(r1),"=r"(r2),"=r"(r3) : "r"(addr))
#define LDSM_X2(r0,r1,addr) \
    asm volatile("ldmatrix.sync.aligned.m8n8.x2.shared.b16 {%0,%1}, [%2];" \
        : "=r"(r0),"=r"(r1) : "r"(addr))
#define MMA16816(c0,c1,c2,c3,a0,a1,a2,a3,b0,b1) \
    asm volatile("mma.sync.aligned.m16n8k16.row.col.f32.bf16.bf16.f32 " \
        "{%0,%1,%2,%3}, {%4,%5,%6,%7}, {%8,%9}, {%0,%1,%2,%3};" \
        : "+f"(c0),"+f"(c1),"+f"(c2),"+f"(c3) \
        : "r"(a0),"r"(a1),"r"(a2),"r"(a3),"r"(b0),"r"(b1))

// ---------------- encoder: z = tanh(x@W1+b1)@W2 + b2 ----------------
__global__ __launch_bounds__(256) void enc_kernel(
    const float* __restrict__ x, const float* __restrict__ W1,
    const float* __restrict__ b1, const float* __restrict__ W2,
    const float* __restrict__ b2)
{
    __shared__ float xs[32][33];
    __shared__ __align__(16) float ws[32][NH];
    __shared__ float hs[32][NH+1];
    __shared__ float w2s[NH*DL];

    const int tid = threadIdx.x;
    const int rowBase = blockIdx.x * 32;
    const int rg = tid >> 4;
    const int cg = tid & 15;

    for (int t = tid; t < NH*DL; t += 256) w2s[t] = W2[t];

    float acc[2][8];
    #pragma unroll
    for (int a=0;a<2;a++)
        #pragma unroll
        for (int u=0;u<8;u++) acc[a][u]=0.f;

    for (int k0 = 0; k0 < DIN; k0 += 32) {
        for (int t = tid; t < 32*32; t += 256) {
            int r = t >> 5, k = t & 31;
            int kk = k0 + k;
            xs[r][k] = (kk < DIN) ? x[(size_t)(rowBase + r)*DIN + kk] : 0.f;
        }
        for (int t = tid; t < 32*NH; t += 256) {
            int k = t >> 7, c = t & (NH-1);
            int kk = k0 + k;
            ws[k][c] = (kk < DIN) ? W1[(size_t)kk*NH + c] : 0.f;
        }
        __syncthreads();
        #pragma unroll
        for (int kk = 0; kk < 32; kk++) {
            float x0 = xs[rg*2+0][kk];
            float x1 = xs[rg*2+1][kk];
            float4 w0 = *(const float4*)&ws[kk][cg*8];
            float4 w1 = *(const float4*)&ws[kk][cg*8+4];
            acc[0][0] = fmaf(x0, w0.x, acc[0][0]);
            acc[0][1] = fmaf(x0, w0.y, acc[0][1]);
            acc[0][2] = fmaf(x0, w0.z, acc[0][2]);
            acc[0][3] = fmaf(x0, w0.w, acc[0][3]);
            acc[0][4] = fmaf(x0, w1.x, acc[0][4]);
            acc[0][5] = fmaf(x0, w1.y, acc[0][5]);
            acc[0][6] = fmaf(x0, w1.z, acc[0][6]);
            acc[0][7] = fmaf(x0, w1.w, acc[0][7]);
            acc[1][0] = fmaf(x1, w0.x, acc[1][0]);
            acc[1][1] = fmaf(x1, w0.y, acc[1][1]);
            acc[1][2] = fmaf(x1, w0.z, acc[1][2]);
            acc[1][3] = fmaf(x1, w0.w, acc[1][3]);
            acc[1][4] = fmaf(x1, w1.x, acc[1][4]);
            acc[1][5] = fmaf(x1, w1.y, acc[1][5]);
            acc[1][6] = fmaf(x1, w1.z, acc[1][6]);
            acc[1][7] = fmaf(x1, w1.w, acc[1][7]);
        }
        __syncthreads();
    }
    #pragma unroll
    for (int a=0;a<2;a++){
        int r = rg*2+a;
        #pragma unroll
        for (int u=0;u<8;u++){
            int c = cg*8+u;
            hs[r][c] = tanh_acc(acc[a][u] + b1[c]);
        }
    }
    __syncthreads();
    {
        int r = tid >> 3;
        int o = tid & 7;
        float s = b2[o];
        #pragma unroll 16
        for (int k=0;k<NH;k++) s = fmaf(hs[r][k], w2s[k*DL+o], s);
        g_z[(size_t)(rowBase + r)*DL + o] = s;
    }
}

// ---- pm field (4 steps), quad-parallel centers ----
__device__ __forceinline__ void pm_quad(float zr[DL], const float* cs,
                                        const float* ms, int q)
{
    #pragma unroll
    for (int step=0; step<4; step++){
        float n = 0.f;
        float g[DL] = {0.f,0.f,0.f,0.f,0.f,0.f,0.f,0.f};
        #pragma unroll
        for (int cc=0;cc<4;cc++){
            int c = q*4 + cc;
            float rv[DL]; float r2 = 1e-4f;
            #pragma unroll
            for (int k=0;k<DL;k++){ rv[k] = zr[k]-cs[c*DL+k]; r2 = fmaf(rv[k],rv[k],r2); }
            float rinv = rsqrt_acc(r2);
            float mr = ms[c]*rinv;
            n += mr;
            float w = mr*rinv*rinv;
            #pragma unroll
            for (int k=0;k<DL;k++) g[k] = fmaf(-w, rv[k], g[k]);
        }
        #pragma unroll
        for (int off=1; off<4; off<<=1){
            n += __shfl_xor_sync(0xffffffffu, n, off);
            #pragma unroll
            for (int k=0;k<DL;k++) g[k] += __shfl_xor_sync(0xffffffffu, g[k], off);
        }
        float s = 0.15f * rcp_acc(n + 1.0f);
        #pragma unroll
        for (int k=0;k<DL;k++)
            zr[k] = fminf(fmaxf(fmaf(s, g[k], zr[k]), -3.f), 3.f);
    }
}

// ---- hpre = 0.9*hc + 0.1*tanh(z@Wp+bp) for 8 channels; also write bf16 g_hT ----
__device__ __forceinline__ void h_update_store(const float zr[DL], const float* wps,
                                               const float* bps, int row, int c0,
                                               float4 hc0, float4 hc1)
{
    float a8[8];
    #pragma unroll
    for (int u=0;u<8;u++) a8[u] = bps[c0+u];
    #pragma unroll
    for (int k=0;k<DL;k++){
        float zk = zr[k];
        #pragma unroll
        for (int u=0;u<8;u++) a8[u] = fmaf(zk, wps[k*CH + c0 + u], a8[u]);
    }
    float hv[8];
    hv[0] = fmaf(0.9f, hc0.x, 0.1f*tanh_acc(a8[0]));
    hv[1] = fmaf(0.9f, hc0.y, 0.1f*tanh_acc(a8[1]));
    hv[2] = fmaf(0.9f, hc0.z, 0.1f*tanh_acc(a8[2]));
    hv[3] = fmaf(0.9f, hc0.w, 0.1f*tanh_acc(a8[3]));
    hv[4] = fmaf(0.9f, hc1.x, 0.1f*tanh_acc(a8[4]));
    hv[5] = fmaf(0.9f, hc1.y, 0.1f*tanh_acc(a8[5]));
    hv[6] = fmaf(0.9f, hc1.z, 0.1f*tanh_acc(a8[6]));
    hv[7] = fmaf(0.9f, hc1.w, 0.1f*tanh_acc(a8[7]));
    *(float4*)&g_hpre[(size_t)row*CH + c0]     = make_float4(hv[0],hv[1],hv[2],hv[3]);
    *(float4*)&g_hpre[(size_t)row*CH + c0 + 4] = make_float4(hv[4],hv[5],hv[6],hv[7]);
    // bf16 transposed + SW128-swizzled per 64-j chunk for the MMA B operand
    int jl = row & 63;
    unsigned gbase = (unsigned)(row >> 6) * 4096u;
    #pragma unroll
    for (int u=0;u<8;u++){
        unsigned off = (unsigned)((c0+u)*128 + jl*2);
        *(__nv_bfloat16*)&g_hT[gbase + SWZ128(off)] = __float2bfloat16(hv[u]);
    }
}

// ------------- prep: z=pm(z0), sq, hpre (h starts at 0); 4 threads/row -------------
__global__ __launch_bounds__(128) void prep_kernel(
    const float* __restrict__ centers, const float* __restrict__ mus,
    const float* __restrict__ Wp, const float* __restrict__ bp)
{
    __shared__ float cs[NC*DL];
    __shared__ float ms[NC];
    __shared__ float wps[DL*CH];
    __shared__ float bps[CH];
    const int tid = threadIdx.x;
    if (tid < NC*DL) cs[tid] = centers[tid];
    if (tid < NC) ms[tid] = mus[tid];
    for (int t = tid; t < DL*CH; t += 128) wps[t] = Wp[t];
    if (tid < CH) bps[tid] = bp[tid];
    __syncthreads();

    const int row = blockIdx.x*32 + (tid >> 2);
    const int q   = tid & 3;

    float zr[DL];
    {
        float4 a = *(const float4*)&g_z[row*DL];
        float4 b = *(const float4*)&g_z[row*DL+4];
        zr[0]=a.x; zr[1]=a.y; zr[2]=a.z; zr[3]=a.w;
        zr[4]=b.x; zr[5]=b.y; zr[6]=b.z; zr[7]=b.w;
    }
    pm_quad(zr, cs, ms, q);
    if (q == 0){
        float s2 = 0.f;
        #pragma unroll
        for (int k=0;k<DL;k++) s2 = fmaf(zr[k], zr[k], s2);
        g_sq[row] = s2;
        *(float4*)&g_z[row*DL]   = make_float4(zr[0],zr[1],zr[2],zr[3]);
        *(float4*)&g_z[row*DL+4] = make_float4(zr[4],zr[5],zr[6],zr[7]);
    }
    float4 z4 = make_float4(0.f,0.f,0.f,0.f);
    h_update_store(zr, wps, bps, row, q*8, z4, z4);
}

// ---------- lateral via warp MMA: part[js][i][:] = sum_{j in split} K(i,j)*h[j][:] ----------
__global__ __launch_bounds__(256,2) void lateral_mma_kernel()
{
    __shared__ __align__(16) char Ks[ITILE*128];     // 128 x 64 bf16, SW128 rows
    __shared__ __align__(16) char Hs[CH*128];        // 32 x 64 bf16 (B^T), SW128 rows
    __shared__ __align__(16) unsigned long long zjd[KC*8];
    __shared__ __align__(16) unsigned long long sjd[KC];

    const int tid  = threadIdx.x;
    const int wid  = tid >> 5;
    const int lane = tid & 31;
    const int i0 = blockIdx.x * ITILE;
    const int jbase = blockIdx.y * JRANGE;

    // K-compute mapping: 2 i-rows (ip, ip+64) x 16 j per thread
    const int ip = tid & 63;
    const int jg = tid >> 6;

    unsigned long long zp[8];
    unsigned long long nsq;
    {
        int ia = i0 + ip, ib = ia + 64;
        float4 a = ((const float4*)g_z)[(size_t)ia*2];
        float4 b = ((const float4*)g_z)[(size_t)ia*2+1];
        float4 c = ((const float4*)g_z)[(size_t)ib*2];
        float4 d = ((const float4*)g_z)[(size_t)ib*2+1];
        PACK2(zp[0], a.x, c.x); PACK2(zp[1], a.y, c.y);
        PACK2(zp[2], a.z, c.z); PACK2(zp[3], a.w, c.w);
        PACK2(zp[4], b.x, d.x); PACK2(zp[5], b.y, d.y);
        PACK2(zp[6], b.z, d.z); PACK2(zp[7], b.w, d.w);
        PACK2(nsq, CI_F*g_sq[ia], CI_F*g_sq[ib]);
    }

    // ldmatrix address bases
    const uint32_t KsB = smem_u32(Ks);
    const uint32_t HsB = smem_u32(Hs);
    const int arow  = wid*16 + (lane & 15);
    const int acolh = lane >> 4;                 // 0/1 (16B half within 32B k-step)
    const int brow  = lane & 7;
    const int bcolh = (lane >> 3) & 1;

    float acc[4][4];
    #pragma unroll
    for (int n=0;n<4;n++)
        #pragma unroll
        for (int r=0;r<4;r++) acc[n][r] = 0.f;

    for (int c = 0; c < NCH; c++){
        const int j0g = jbase + c*KC;
        __syncthreads();   // previous chunk's MMA reads done before restaging
        // ---- stage zjd/sjd + H tile (pre-swizzled linear 4KB) ----
        if (tid < 128){
            int j = tid >> 1, half = tid & 1;
            float4 v = *(const float4*)&g_z[(size_t)(j0g + j)*8 + half*4];
            unsigned long long p0,p1,p2,p3;
            float s0 = M2CI_F*v.x, s1 = M2CI_F*v.y, s2 = M2CI_F*v.z, s3 = M2CI_F*v.w;
            PACK2(p0, s0, s0); PACK2(p1, s1, s1); PACK2(p2, s2, s2); PACK2(p3, s3, s3);
            ulonglong2* dst = (ulonglong2*)&zjd[j*8 + half*4];
            dst[0] = make_ulonglong2(p0, p1);
            dst[1] = make_ulonglong2(p2, p3);
            if (half == 0){
                float sv = CI_F * g_sq[j0g + j];
                unsigned long long ps; PACK2(ps, sv, sv);
                sjd[j] = ps;
            }
        }
        {
            const uint4* src = (const uint4*)&g_hT[(size_t)(j0g >> 6) * 4096];
            ((uint4*)Hs)[tid] = src[tid];
        }
        __syncthreads();

        // ---- compute K tile (bf16) into Ks with SW128 rows ----
        const int jb = jg*16;
        #pragma unroll
        for (int half = 0; half < 2; half++){
            unsigned kb0[4], kb1[4];
            #pragma unroll
            for (int jp = 0; jp < 4; jp++){
                int j0l = jb + half*8 + jp*2;
                int j1l = j0l + 1;
                unsigned long long ea0, ea1;
                ADD2(ea0, sjd[j0l], nsq);
                ADD2(ea1, sjd[j1l], nsq);
                const ulonglong2* za = (const ulonglong2*)&zjd[j0l*8];
                const ulonglong2* zb = (const ulonglong2*)&zjd[j1l*8];
                #pragma unroll
                for (int k=0;k<4;k++){
                    ulonglong2 va = za[k];
                    ulonglong2 vb = zb[k];
                    FMA2(ea0, zp[2*k],   va.x, ea0);
                    FMA2(ea0, zp[2*k+1], va.y, ea0);
                    FMA2(ea1, zp[2*k],   vb.x, ea1);
                    FMA2(ea1, zp[2*k+1], vb.y, ea1);
                }
                float a00,a10,a01,a11;
                UNPACK2(a00, a10, ea0);
                UNPACK2(a01, a11, ea1);
                float e00 = ex2f(a00), e10 = ex2f(a10), e01 = ex2f(a01), e11 = ex2f(a11);
                float p00 = e00*e00, p10 = e10*e10, p01 = e01*e01, p11 = e11*e11;
                float K00 = fmaf(0.8f, p00*p00, -e00);
                float K10 = fmaf(0.8f, p10*p10, -e10);
                float K01 = fmaf(0.8f, p01*p01, -e01);
                float K11 = fmaf(0.8f, p11*p11, -e11);
                asm("cvt.rn.satfinite.bf16x2.f32 %0, %1, %2;" : "=r"(kb0[jp]) : "f"(K01), "f"(K00));
                asm("cvt.rn.satfinite.bf16x2.f32 %0, %1, %2;" : "=r"(kb1[jp]) : "f"(K11), "f"(K10));
            }
            unsigned byte0 = (unsigned)(ip*128      + jb*2 + half*16);
            unsigned byte1 = (unsigned)((ip+64)*128 + jb*2 + half*16);
            *(uint4*)(Ks + SWZ128(byte0)) = make_uint4(kb0[0],kb0[1],kb0[2],kb0[3]);
            *(uint4*)(Ks + SWZ128(byte1)) = make_uint4(kb1[0],kb1[1],kb1[2],kb1[3]);
        }
        __syncthreads();

        // ---- warp MMA: D[16x32 per warp] += K[16x64] * H[32x64]^T ----
        #pragma unroll
        for (int kk = 0; kk < 4; kk++){
            unsigned a0,a1,a2,a3;
            uint32_t aaddr = KsB + SWZ128((unsigned)(arow*128 + kk*32 + acolh*16));
            LDSM_X4(a0,a1,a2,a3, aaddr);
            #pragma unroll
            for (int n = 0; n < 4; n++){
                unsigned b0,b1;
                uint32_t baddr = HsB + SWZ128((unsigned)((n*8 + brow)*128 + kk*32 + bcolh*16));
                LDSM_X2(b0,b1, baddr);
                MMA16816(acc[n][0],acc[n][1],acc[n][2],acc[n][3], a0,a1,a2,a3, b0,b1);
            }
        }
    }

    // ---- epilogue: write D to g_part ----
    {
        int m0 = i0 + wid*16 + (lane >> 2);
        int nc = 2*(lane & 3);
        float* d0 = &g_part[((size_t)blockIdx.y*NB + m0)*CH];
        float* d1 = &g_part[((size_t)blockIdx.y*NB + m0 + 8)*CH];
        #pragma unroll
        for (int n = 0; n < 4; n++){
            *(float2*)&d0[n*8 + nc] = make_float2(acc[n][0], acc[n][1]);
            *(float2*)&d1[n*8 + nc] = make_float2(acc[n][2], acc[n][3]);
        }
    }
}

// ------- fused: hcomb = hpre + 0.05*sum(part); z = pm(z); hpre/hT update -------
__global__ __launch_bounds__(128) void fused_kernel(
    const float* __restrict__ centers, const float* __restrict__ mus,
    const float* __restrict__ Wp, const float* __restrict__ bp)
{
    __shared__ float cs[NC*DL];
    __shared__ float ms[NC];
    __shared__ float wps[DL*CH];
    __shared__ float bps[CH];
    const int tid = threadIdx.x;
    if (tid < NC*DL) cs[tid] = centers[tid];
    if (tid < NC) ms[tid] = mus[tid];
    for (int t = tid; t < DL*CH; t += 128) wps[t] = Wp[t];
    if (tid < CH) bps[tid] = bp[tid];
    __syncthreads();

    const int row = blockIdx.x*32 + (tid >> 2);
    const int q   = tid & 3;
    const int c0  = q*8;

    float t0x=0.f,t0y=0.f,t0z=0.f,t0w=0.f, t1x=0.f,t1y=0.f,t1z=0.f,t1w=0.f;
    #pragma unroll
    for (int c=0;c<NCHUNK;c++){
        const float* base = &g_part[((size_t)c*NB + row)*CH + c0];
        float4 p0 = *(const float4*)base;
        float4 p1 = *(const float4*)(base+4);
        t0x+=p0.x; t0y+=p0.y; t0z+=p0.z; t0w+=p0.w;
        t1x+=p1.x; t1y+=p1.y; t1z+=p1.z; t1w+=p1.w;
    }
    float4 h0 = *(const float4*)&g_hpre[(size_t)row*CH + c0];
    float4 h1 = *(const float4*)&g_hpre[(size_t)row*CH + c0 + 4];
    float4 hc0, hc1;
    hc0.x = fmaf(0.05f, t0x, h0.x); hc0.y = fmaf(0.05f, t0y, h0.y);
    hc0.z = fmaf(0.05f, t0z, h0.z); hc0.w = fmaf(0.05f, t0w, h0.w);
    hc1.x = fmaf(0.05f, t1x, h1.x); hc1.y = fmaf(0.05f, t1y, h1.y);
    hc1.z = fmaf(0.05f, t1z, h1.z); hc1.w = fmaf(0.05f, t1w, h1.w);

    float zr[DL];
    {
        float4 a = *(const float4*)&g_z[row*DL];
        float4 b = *(const float4*)&g_z[row*DL+4];
        zr[0]=a.x; zr[1]=a.y; zr[2]=a.z; zr[3]=a.w;
        zr[4]=b.x; zr[5]=b.y; zr[6]=b.z; zr[7]=b.w;
    }
    pm_quad(zr, cs, ms, q);
    if (q == 0){
        float s2 = 0.f;
        #pragma unroll
        for (int k=0;k<DL;k++) s2 = fmaf(zr[k], zr[k], s2);
        g_sq[row] = s2;
        *(float4*)&g_z[row*DL]   = make_float4(zr[0],zr[1],zr[2],zr[3]);
        *(float4*)&g_z[row*DL+4] = make_float4(zr[4],zr[5],zr[6],zr[7]);
    }
    h_update_store(zr, wps, bps, row, c0, hc0, hc1);
}

// ------- final: hcomb = hpre + 0.05*sum(part); y = hcomb @ Wr + br -------
__global__ __launch_bounds__(128) void final_kernel(
    const float* __restrict__ Wr, const float* __restrict__ br,
    float* __restrict__ y)
{
    __shared__ float wrs[CH*DOUT];
    __shared__ float brs[DOUT];
    const int tid = threadIdx.x;
    for (int t=tid; t<CH*DOUT; t+=128) wrs[t] = Wr[t];
    if (tid < DOUT) brs[tid] = br[tid];
    __syncthreads();

    const int row = blockIdx.x*32 + (tid >> 2);
    const int q   = tid & 3;
    const int c0  = q*8;

    float t0x=0.f,t0y=0.f,t0z=0.f,t0w=0.f, t1x=0.f,t1y=0.f,t1z=0.f,t1w=0.f;
    #pragma unroll
    for (int c=0;c<NCHUNK;c++){
        const float* base = &g_part[((size_t)c*NB + row)*CH + c0];
        float4 p0 = *(const float4*)base;
        float4 p1 = *(const float4*)(base+4);
        t0x+=p0.x; t0y+=p0.y; t0z+=p0.z; t0w+=p0.w;
        t1x+=p1.x; t1y+=p1.y; t1z+=p1.z; t1w+=p1.w;
    }
    float4 h0 = *(const float4*)&g_hpre[(size_t)row*CH + c0];
    float4 h1 = *(const float4*)&g_hpre[(size_t)row*CH + c0 + 4];
    float hc[8];
    hc[0] = fmaf(0.05f, t0x, h0.x); hc[1] = fmaf(0.05f, t0y, h0.y);
    hc[2] = fmaf(0.05f, t0z, h0.z); hc[3] = fmaf(0.05f, t0w, h0.w);
    hc[4] = fmaf(0.05f, t1x, h1.x); hc[5] = fmaf(0.05f, t1y, h1.y);
    hc[6] = fmaf(0.05f, t1z, h1.z); hc[7] = fmaf(0.05f, t1w, h1.w);

    float o[DOUT];
    #pragma unroll
    for (int d=0; d<DOUT; d++) o[d] = 0.f;
    #pragma unroll
    for (int u=0;u<8;u++){
        float hcu = hc[u];
        #pragma unroll
        for (int d=0; d<DOUT; d++) o[d] = fmaf(hcu, wrs[(c0+u)*DOUT+d], o[d]);
    }
    #pragma unroll
    for (int off=1; off<4; off<<=1){
        #pragma unroll
        for (int d=0; d<DOUT; d++) o[d] += __shfl_xor_sync(0xffffffffu, o[d], off);
    }
    if (q == 0){
        #pragma unroll
        for (int d=0; d<DOUT; d++) y[(size_t)row*DOUT + d] = o[d] + brs[d];
    }
}

// ---------------- launch ----------------
extern "C" void kernel_launch(void* const* d_in, const int* in_sizes, int n_in,
                              void* d_out, int out_size)
{
    const float* x       = (const float*)d_in[0];
    const float* W1      = (const float*)d_in[1];
    const float* b1      = (const float*)d_in[2];
    const float* W2      = (const float*)d_in[3];
    const float* b2      = (const float*)d_in[4];
    const float* centers = (const float*)d_in[5];
    const float* mus     = (const float*)d_in[6];
    const float* Wp      = (const float*)d_in[7];
    const float* bp      = (const float*)d_in[8];
    const float* Wr      = (const float*)d_in[9];
    const float* br      = (const float*)d_in[10];
    float* y = (float*)d_out;

    enc_kernel<<<NB/32, 256>>>(x, W1, b1, W2, b2);
    prep_kernel<<<NB/32, 128>>>(centers, mus, Wp, bp);
    for (int t = 1; t <= TSTEPS; t++){
        lateral_mma_kernel<<<dim3(NB/ITILE, NJS), 256>>>();
        if (t < TSTEPS)
            fused_kernel<<<NB/32, 128>>>(centers, mus, Wp, bp);
    }
    final_kernel<<<NB/32, 128>>>(Wr, br, y);
}

// round 7
// speedup vs baseline: 1.9312x; 1.1445x over previous
#include <cuda_runtime.h>
#include <cuda_bf16.h>
#include <cstdint>

#define NB   4096
#define DIN  784
#define NH   128
#define DL   8
#define NC   16
#define CH   32
#define DOUT 10
#define NCHUNK 8
#define TSTEPS 5

// lateral tiling
#define ITILE 128
#define KC    64
#define NJS   8
#define JRANGE (NB/NJS)
#define NCH   (JRANGE/KC)

#define HT_ROW 144              // 72 bf16 per hT row (padded for conflict-free LDS)
#define HT_CHUNK (CH*HT_ROW)    // 4608 B per 64-j chunk
#define ZJ_ROW 48               // 24 bf16 per zj row (16 used)

// ---------------- scratch ----------------
__device__ __align__(16) float g_z[NB*DL];
__device__ float g_sq[NB];                       // CI * |z|^2
__device__ __align__(16) __nv_bfloat16 g_zhl[NB*16];   // [hi0..hi7, lo0..lo7]
__device__ __align__(16) float g_hpre[NB*CH];
__device__ __align__(16) char  g_hT[(NB/KC)*HT_CHUNK]; // bf16 [chunk][ch][72]
__device__ __align__(16) float g_part[(size_t)NCHUNK*NB*CH];

// ---------------- math helpers ----------
__device__ __forceinline__ float ex2f(float x){
    float y; asm("ex2.approx.f32 %0, %1;" : "=f"(y) : "f"(x)); return y;
}
__device__ __forceinline__ float rcp_acc(float x){
    float r; asm("rcp.approx.f32 %0, %1;" : "=f"(r) : "f"(x));
    return r * fmaf(-x, r, 2.0f);
}
__device__ __forceinline__ float rsqrt_acc(float x){
    float r; asm("rsqrt.approx.f32 %0, %1;" : "=f"(r) : "f"(x));
    float e = x * r;
    return r * fmaf(-0.5f, e * r, 1.5f);
}
__device__ __forceinline__ float tanh_acc(float x){
    float ax = fabsf(x);
    float t  = ex2f(-2.8853900817779268f * ax);
    float y  = (1.0f - t) * rcp_acc(1.0f + t);
    return copysignf(y, x);
}

// CI = -log2(e)/(2*1.2^2)
#define CI_F   (-0.50093577808644655f)
#define M2CI_F ( 1.0018715561728931f)

__device__ __forceinline__ uint32_t smem_u32(const void* p){
    uint32_t a;
    asm("{ .reg .u64 t; cvta.to.shared.u64 t, %1; cvt.u32.u64 %0, t; }" : "=r"(a) : "l"(p));
    return a;
}
#define MMA16816(c0,c1,c2,c3,a0,a1,a2,a3,b0,b1) \
    asm volatile("mma.sync.aligned.m16n8k16.row.col.f32.bf16.bf16.f32 " \
        "{%0,%1,%2,%3}, {%4,%5,%6,%7}, {%8,%9}, {%0,%1,%2,%3};" \
        : "+f"(c0),"+f"(c1),"+f"(c2),"+f"(c3) \
        : "r"(a0),"r"(a1),"r"(a2),"r"(a3),"r"(b0),"r"(b1))
#define CVT_BF2(d,hi,lo) asm("cvt.rn.satfinite.bf16x2.f32 %0, %1, %2;" : "=r"(d) : "f"(hi), "f"(lo))

// ---------------- encoder ----------------
__global__ __launch_bounds__(256) void enc_kernel(
    const float* __restrict__ x, const float* __restrict__ W1,
    const float* __restrict__ b1, const float* __restrict__ W2,
    const float* __restrict__ b2)
{
    __shared__ float xs[32][33];
    __shared__ __align__(16) float ws[32][NH];
    __shared__ float hs[32][NH+1];
    __shared__ float w2s[NH*DL];

    const int tid = threadIdx.x;
    const int rowBase = blockIdx.x * 32;
    const int rg = tid >> 4;
    const int cg = tid & 15;

    for (int t = tid; t < NH*DL; t += 256) w2s[t] = W2[t];

    float acc[2][8];
    #pragma unroll
    for (int a=0;a<2;a++)
        #pragma unroll
        for (int u=0;u<8;u++) acc[a][u]=0.f;

    for (int k0 = 0; k0 < DIN; k0 += 32) {
        for (int t = tid; t < 32*32; t += 256) {
            int r = t >> 5, k = t & 31;
            int kk = k0 + k;
            xs[r][k] = (kk < DIN) ? x[(size_t)(rowBase + r)*DIN + kk] : 0.f;
        }
        for (int t = tid; t < 32*NH; t += 256) {
            int k = t >> 7, c = t & (NH-1);
            int kk = k0 + k;
            ws[k][c] = (kk < DIN) ? W1[(size_t)kk*NH + c] : 0.f;
        }
        __syncthreads();
        #pragma unroll
        for (int kk = 0; kk < 32; kk++) {
            float x0 = xs[rg*2+0][kk];
            float x1 = xs[rg*2+1][kk];
            float4 w0 = *(const float4*)&ws[kk][cg*8];
            float4 w1 = *(const float4*)&ws[kk][cg*8+4];
            acc[0][0] = fmaf(x0, w0.x, acc[0][0]);
            acc[0][1] = fmaf(x0, w0.y, acc[0][1]);
            acc[0][2] = fmaf(x0, w0.z, acc[0][2]);
            acc[0][3] = fmaf(x0, w0.w, acc[0][3]);
            acc[0][4] = fmaf(x0, w1.x, acc[0][4]);
            acc[0][5] = fmaf(x0, w1.y, acc[0][5]);
            acc[0][6] = fmaf(x0, w1.z, acc[0][6]);
            acc[0][7] = fmaf(x0, w1.w, acc[0][7]);
            acc[1][0] = fmaf(x1, w0.x, acc[1][0]);
            acc[1][1] = fmaf(x1, w0.y, acc[1][1]);
            acc[1][2] = fmaf(x1, w0.z, acc[1][2]);
            acc[1][3] = fmaf(x1, w0.w, acc[1][3]);
            acc[1][4] = fmaf(x1, w1.x, acc[1][4]);
            acc[1][5] = fmaf(x1, w1.y, acc[1][5]);
            acc[1][6] = fmaf(x1, w1.z, acc[1][6]);
            acc[1][7] = fmaf(x1, w1.w, acc[1][7]);
        }
        __syncthreads();
    }
    #pragma unroll
    for (int a=0;a<2;a++){
        int r = rg*2+a;
        #pragma unroll
        for (int u=0;u<8;u++){
            int c = cg*8+u;
            hs[r][c] = tanh_acc(acc[a][u] + b1[c]);
        }
    }
    __syncthreads();
    {
        int r = tid >> 3;
        int o = tid & 7;
        float s = b2[o];
        #pragma unroll 16
        for (int k=0;k<NH;k++) s = fmaf(hs[r][k], w2s[k*DL+o], s);
        g_z[(size_t)(rowBase + r)*DL + o] = s;
    }
}

// ---- pm field (4 steps), 8 threads per row (2 centers each) ----
__device__ __forceinline__ void pm_oct(float zr[DL], const float* cs,
                                       const float* ms, int o)
{
    #pragma unroll
    for (int step=0; step<4; step++){
        float n = 0.f;
        float g[DL] = {0.f,0.f,0.f,0.f,0.f,0.f,0.f,0.f};
        #pragma unroll
        for (int cc=0;cc<2;cc++){
            int c = o*2 + cc;
            float rv[DL]; float r2 = 1e-4f;
            #pragma unroll
            for (int k=0;k<DL;k++){ rv[k] = zr[k]-cs[c*DL+k]; r2 = fmaf(rv[k],rv[k],r2); }
            float rinv = rsqrt_acc(r2);
            float mr = ms[c]*rinv;
            n += mr;
            float w = mr*rinv*rinv;
            #pragma unroll
            for (int k=0;k<DL;k++) g[k] = fmaf(-w, rv[k], g[k]);
        }
        #pragma unroll
        for (int off=1; off<8; off<<=1){
            n += __shfl_xor_sync(0xffffffffu, n, off);
            #pragma unroll
            for (int k=0;k<DL;k++) g[k] += __shfl_xor_sync(0xffffffffu, g[k], off);
        }
        float s = 0.15f * rcp_acc(n + 1.0f);
        #pragma unroll
        for (int k=0;k<DL;k++)
            zr[k] = fminf(fmaxf(fmaf(s, g[k], zr[k]), -3.f), 3.f);
    }
}

// ---- z side-products: g_z, g_sq(CI-scaled), g_zhl (hi/lo bf16) ----
__device__ __forceinline__ void z_store(const float zr[DL], int row)
{
    float s2 = 0.f;
    #pragma unroll
    for (int k=0;k<DL;k++) s2 = fmaf(zr[k], zr[k], s2);
    g_sq[row] = CI_F * s2;
    *(float4*)&g_z[row*DL]   = make_float4(zr[0],zr[1],zr[2],zr[3]);
    *(float4*)&g_z[row*DL+4] = make_float4(zr[4],zr[5],zr[6],zr[7]);
    __nv_bfloat16 hi[8], lo[8];
    #pragma unroll
    for (int k=0;k<DL;k++){
        hi[k] = __float2bfloat16(zr[k]);
        lo[k] = __float2bfloat16(zr[k] - __bfloat162float(hi[k]));
    }
    __nv_bfloat16* dst = &g_zhl[row*16];
    *(uint4*)dst       = *(uint4*)hi;
    *(uint4*)(dst + 8) = *(uint4*)lo;
}

// ---- hpre = 0.9*hc + 0.1*tanh(z@Wp+bp) for 4 channels; write g_hT (padded) ----
__device__ __forceinline__ void h_update4(const float zr[DL], const float* wps,
                                          const float* bps, int row, int c0,
                                          float4 hc)
{
    float a4[4];
    #pragma unroll
    for (int u=0;u<4;u++) a4[u] = bps[c0+u];
    #pragma unroll
    for (int k=0;k<DL;k++){
        float zk = zr[k];
        #pragma unroll
        for (int u=0;u<4;u++) a4[u] = fmaf(zk, wps[k*CH + c0 + u], a4[u]);
    }
    float4 hv;
    hv.x = fmaf(0.9f, hc.x, 0.1f*tanh_acc(a4[0]));
    hv.y = fmaf(0.9f, hc.y, 0.1f*tanh_acc(a4[1]));
    hv.z = fmaf(0.9f, hc.z, 0.1f*tanh_acc(a4[2]));
    hv.w = fmaf(0.9f, hc.w, 0.1f*tanh_acc(a4[3]));
    *(float4*)&g_hpre[(size_t)row*CH + c0] = hv;
    int jl = row & 63;
    char* base = g_hT + (size_t)(row >> 6) * HT_CHUNK + jl*2;
    *(__nv_bfloat16*)(base + (c0+0)*HT_ROW) = __float2bfloat16(hv.x);
    *(__nv_bfloat16*)(base + (c0+1)*HT_ROW) = __float2bfloat16(hv.y);
    *(__nv_bfloat16*)(base + (c0+2)*HT_ROW) = __float2bfloat16(hv.z);
    *(__nv_bfloat16*)(base + (c0+3)*HT_ROW) = __float2bfloat16(hv.w);
}

// ------------- prep: z=pm(z0), side-products, hpre (h=0) -------------
__global__ __launch_bounds__(256) void prep_kernel(
    const float* __restrict__ centers, const float* __restrict__ mus,
    const float* __restrict__ Wp, const float* __restrict__ bp)
{
    __shared__ float cs[NC*DL];
    __shared__ float ms[NC];
    __shared__ float wps[DL*CH];
    __shared__ float bps[CH];
    const int tid = threadIdx.x;
    if (tid < NC*DL) cs[tid] = centers[tid];
    if (tid < NC) ms[tid] = mus[tid];
    if (tid < DL*CH) wps[tid] = Wp[tid];
    if (tid < CH) bps[tid] = bp[tid];
    __syncthreads();

    const int row = blockIdx.x*32 + (tid >> 3);
    const int o   = tid & 7;

    float zr[DL];
    {
        float4 a = *(const float4*)&g_z[row*DL];
        float4 b = *(const float4*)&g_z[row*DL+4];
        zr[0]=a.x; zr[1]=a.y; zr[2]=a.z; zr[3]=a.w;
        zr[4]=b.x; zr[5]=b.y; zr[6]=b.z; zr[7]=b.w;
    }
    pm_oct(zr, cs, ms, o);
    if (o == 0) z_store(zr, row);
    h_update4(zr, wps, bps, row, o*4, make_float4(0.f,0.f,0.f,0.f));
}

// ---------- lateral: HMMA dot (hi/lo) -> K in regs -> HMMA K@H ----------
__global__ __launch_bounds__(256,2) void lateral_mma_kernel()
{
    __shared__ __align__(16) char zjs[KC*ZJ_ROW];      // 3 KB
    __shared__ __align__(16) float csq[KC];
    __shared__ __align__(16) char hTs[HT_CHUNK];       // 4.5 KB

    const int tid  = threadIdx.x;
    const int wid  = tid >> 5;
    const int lane = tid & 31;
    const int grp  = lane >> 2;
    const int t    = lane & 3;
    const int i0 = blockIdx.x * ITILE;
    const int jbase = blockIdx.y * JRANGE;

    const int rowa = i0 + wid*16 + grp;
    const int rowb = rowa + 8;
    uint32_t a0 = *(const uint32_t*)&g_zhl[rowa*16 + 2*t];
    uint32_t a1 = *(const uint32_t*)&g_zhl[rowb*16 + 2*t];
    uint32_t a2 = *(const uint32_t*)&g_zhl[rowa*16 + 8 + 2*t];
    uint32_t a3 = *(const uint32_t*)&g_zhl[rowb*16 + 8 + 2*t];
    const float csia = g_sq[rowa];
    const float csib = g_sq[rowb];

    const uint32_t zjB = smem_u32(zjs);
    const uint32_t hTB = smem_u32(hTs);

    float hacc[4][4];
    #pragma unroll
    for (int n=0;n<4;n++)
        #pragma unroll
        for (int r=0;r<4;r++) hacc[n][r] = 0.f;

    for (int c = 0; c < NCH; c++){
        const int j0g = jbase + c*KC;
        __syncthreads();
        // stage zj hi/lo (48B rows), csq, hT (144B rows)
        if (tid < 128){
            int j = tid >> 1, half = tid & 1;
            uint4 v = *(const uint4*)&g_zhl[(size_t)(j0g + j)*16 + half*8];
            *(uint4*)(zjs + j*ZJ_ROW + half*16) = v;
        }
        if (tid < KC) csq[tid] = g_sq[j0g + tid];
        {
            const uint4* src = (const uint4*)(g_hT + (size_t)(j0g >> 6) * HT_CHUNK);
            for (int s = tid; s < HT_CHUNK/16; s += 256) ((uint4*)hTs)[s] = src[s];
        }
        __syncthreads();

        #pragma unroll
        for (int ks = 0; ks < 4; ks++){
            uint32_t ka[4];
            #pragma unroll
            for (int g = 0; g < 2; g++){
                float cc0=0.f, cc1=0.f, cc2=0.f, cc3=0.f;
                int j = ks*16 + g*8 + grp;
                uint32_t b0, b1;
                asm volatile("ld.shared.b32 %0, [%1];" : "=r"(b0) : "r"(zjB + j*ZJ_ROW + 4*t));
                asm volatile("ld.shared.b32 %0, [%1];" : "=r"(b1) : "r"(zjB + j*ZJ_ROW + 16 + 4*t));
                MMA16816(cc0,cc1,cc2,cc3, a0,a1,a2,a3, b0,b1);   // hi.hi + lo.lo
                MMA16816(cc0,cc1,cc2,cc3, a0,a1,a2,a3, b1,b0);   // hi.lo + lo.hi
                float2 sj = *(const float2*)&csq[ks*16 + g*8 + 2*t];
                float ea0 = fmaf(M2CI_F, cc0, csia + sj.x);
                float ea1 = fmaf(M2CI_F, cc1, csia + sj.y);
                float ea2 = fmaf(M2CI_F, cc2, csib + sj.x);
                float ea3 = fmaf(M2CI_F, cc3, csib + sj.y);
                float e0 = ex2f(ea0), e1 = ex2f(ea1), e2 = ex2f(ea2), e3 = ex2f(ea3);
                float p0 = e0*e0, p1 = e1*e1, p2 = e2*e2, p3 = e3*e3;
                float K0 = fmaf(0.8f, p0*p0, -e0);
                float K1 = fmaf(0.8f, p1*p1, -e1);
                float K2 = fmaf(0.8f, p2*p2, -e2);
                float K3 = fmaf(0.8f, p3*p3, -e3);
                CVT_BF2(ka[g*2+0], K1, K0);   // row a: j-local (2t, 2t+1)
                CVT_BF2(ka[g*2+1], K3, K2);   // row b: j-local (2t, 2t+1)
            }
            // ka is already in A-fragment order:
            //   ka[0]=rowa k0-7, ka[1]=rowb k0-7, ka[2]=rowa k8-15, ka[3]=rowb k8-15
            #pragma unroll
            for (int n = 0; n < 4; n++){
                uint32_t hb0, hb1;
                uint32_t haddr = hTB + (n*8 + grp)*HT_ROW + (ks*16 + 2*t)*2;
                asm volatile("ld.shared.b32 %0, [%1];" : "=r"(hb0) : "r"(haddr));
                asm volatile("ld.shared.b32 %0, [%1];" : "=r"(hb1) : "r"(haddr + 16));
                MMA16816(hacc[n][0],hacc[n][1],hacc[n][2],hacc[n][3],
                         ka[0],ka[1],ka[2],ka[3], hb0, hb1);
            }
        }
    }

    // epilogue
    {
        float* d0 = &g_part[((size_t)blockIdx.y*NB + rowa)*CH];
        float* d1 = &g_part[((size_t)blockIdx.y*NB + rowb)*CH];
        #pragma unroll
        for (int n = 0; n < 4; n++){
            *(float2*)&d0[n*8 + 2*t] = make_float2(hacc[n][0], hacc[n][1]);
            *(float2*)&d1[n*8 + 2*t] = make_float2(hacc[n][2], hacc[n][3]);
        }
    }
}

// ------- fused: hcomb = hpre + 0.05*sum(part); z = pm(z); h/hT update -------
__global__ __launch_bounds__(256) void fused_kernel(
    const float* __restrict__ centers, const float* __restrict__ mus,
    const float* __restrict__ Wp, const float* __restrict__ bp)
{
    __shared__ float cs[NC*DL];
    __shared__ float ms[NC];
    __shared__ float wps[DL*CH];
    __shared__ float bps[CH];
    const int tid = threadIdx.x;
    if (tid < NC*DL) cs[tid] = centers[tid];
    if (tid < NC) ms[tid] = mus[tid];
    if (tid < DL*CH) wps[tid] = Wp[tid];
    if (tid < CH) bps[tid] = bp[tid];
    __syncthreads();

    const int row = blockIdx.x*32 + (tid >> 3);
    const int o   = tid & 7;
    const int c0  = o*4;

    float tx=0.f, ty=0.f, tz=0.f, tw=0.f;
    #pragma unroll
    for (int c=0;c<NCHUNK;c++){
        float4 p = *(const float4*)&g_part[((size_t)c*NB + row)*CH + c0];
        tx+=p.x; ty+=p.y; tz+=p.z; tw+=p.w;
    }
    float4 h0 = *(const float4*)&g_hpre[(size_t)row*CH + c0];
    float4 hc;
    hc.x = fmaf(0.05f, tx, h0.x);
    hc.y = fmaf(0.05f, ty, h0.y);
    hc.z = fmaf(0.05f, tz, h0.z);
    hc.w = fmaf(0.05f, tw, h0.w);

    float zr[DL];
    {
        float4 a = *(const float4*)&g_z[row*DL];
        float4 b = *(const float4*)&g_z[row*DL+4];
        zr[0]=a.x; zr[1]=a.y; zr[2]=a.z; zr[3]=a.w;
        zr[4]=b.x; zr[5]=b.y; zr[6]=b.z; zr[7]=b.w;
    }
    pm_oct(zr, cs, ms, o);
    if (o == 0) z_store(zr, row);
    h_update4(zr, wps, bps, row, c0, hc);
}

// ------- final: hcomb = hpre + 0.05*sum(part); y = hcomb @ Wr + br -------
__global__ __launch_bounds__(128) void final_kernel(
    const float* __restrict__ Wr, const float* __restrict__ br,
    float* __restrict__ y)
{
    __shared__ float wrs[CH*DOUT];
    __shared__ float brs[DOUT];
    const int tid = threadIdx.x;
    for (int t=tid; t<CH*DOUT; t+=128) wrs[t] = Wr[t];
    if (tid < DOUT) brs[tid] = br[tid];
    __syncthreads();

    const int row = blockIdx.x*32 + (tid >> 2);
    const int q   = tid & 3;
    const int c0  = q*8;

    float t0x=0.f,t0y=0.f,t0z=0.f,t0w=0.f, t1x=0.f,t1y=0.f,t1z=0.f,t1w=0.f;
    #pragma unroll
    for (int c=0;c<NCHUNK;c++){
        const float* base = &g_part[((size_t)c*NB + row)*CH + c0];
        float4 p0 = *(const float4*)base;
        float4 p1 = *(const float4*)(base+4);
        t0x+=p0.x; t0y+=p0.y; t0z+=p0.z; t0w+=p0.w;
        t1x+=p1.x; t1y+=p1.y; t1z+=p1.z; t1w+=p1.w;
    }
    float4 h0 = *(const float4*)&g_hpre[(size_t)row*CH + c0];
    float4 h1 = *(const float4*)&g_hpre[(size_t)row*CH + c0 + 4];
    float hc[8];
    hc[0] = fmaf(0.05f, t0x, h0.x); hc[1] = fmaf(0.05f, t0y, h0.y);
    hc[2] = fmaf(0.05f, t0z, h0.z); hc[3] = fmaf(0.05f, t0w, h0.w);
    hc[4] = fmaf(0.05f, t1x, h1.x); hc[5] = fmaf(0.05f, t1y, h1.y);
    hc[6] = fmaf(0.05f, t1z, h1.z); hc[7] = fmaf(0.05f, t1w, h1.w);

    float o[DOUT];
    #pragma unroll
    for (int d=0; d<DOUT; d++) o[d] = 0.f;
    #pragma unroll
    for (int u=0;u<8;u++){
        float hcu = hc[u];
        #pragma unroll
        for (int d=0; d<DOUT; d++) o[d] = fmaf(hcu, wrs[(c0+u)*DOUT+d], o[d]);
    }
    #pragma unroll
    for (int off=1; off<4; off<<=1){
        #pragma unroll
        for (int d=0; d<DOUT; d++) o[d] += __shfl_xor_sync(0xffffffffu, o[d], off);
    }
    if (q == 0){
        #pragma unroll
        for (int d=0; d<DOUT; d++) y[(size_t)row*DOUT + d] = o[d] + brs[d];
    }
}

// ---------------- launch ----------------
extern "C" void kernel_launch(void* const* d_in, const int* in_sizes, int n_in,
                              void* d_out, int out_size)
{
    const float* x       = (const float*)d_in[0];
    const float* W1      = (const float*)d_in[1];
    const float* b1      = (const float*)d_in[2];
    const float* W2      = (const float*)d_in[3];
    const float* b2      = (const float*)d_in[4];
    const float* centers = (const float*)d_in[5];
    const float* mus     = (const float*)d_in[6];
    const float* Wp      = (const float*)d_in[7];
    const float* bp      = (const float*)d_in[8];
    const float* Wr      = (const float*)d_in[9];
    const float* br      = (const float*)d_in[10];
    float* y = (float*)d_out;

    enc_kernel<<<NB/32, 256>>>(x, W1, b1, W2, b2);
    prep_kernel<<<NB/32, 256>>>(centers, mus, Wp, bp);
    for (int t = 1; t <= TSTEPS; t++){
        lateral_mma_kernel<<<dim3(NB/ITILE, NJS), 256>>>();
        if (t < TSTEPS)
            fused_kernel<<<NB/32, 256>>>(centers, mus, Wp, bp);
    }
    final_kernel<<<NB/32, 128>>>(Wr, br, y);
}

// round 8
// speedup vs baseline: 1.9481x; 1.0088x over previous
#include <cuda_runtime.h>
#include <cuda_bf16.h>
#include <cstdint>

#define NB   4096
#define DIN  784
#define NH   128
#define DL   8
#define NC   16
#define CH   32
#define DOUT 10
#define NCHUNK 16
#define TSTEPS 5

// lateral tiling
#define ITILE 128
#define KC    64
#define NJS   16
#define JRANGE (NB/NJS)     // 256
#define NCH   (JRANGE/KC)   // 4

#define HT_ROW 144              // 72 bf16 per hT row (padded, conflict-free LDS)
#define HT_CHUNK (CH*HT_ROW)    // 4608 B per 64-j chunk
#define ZJ_ROW 48               // 24 bf16 per zj row (16 used)

// ---------------- scratch ----------------
__device__ __align__(16) float g_z[NB*DL];
__device__ float g_sq[NB];                       // CI * |z|^2
__device__ __align__(16) __nv_bfloat16 g_zhl[NB*16];   // [hi0..hi7, lo0..lo7]
__device__ __align__(16) float g_hpre[NB*CH];
__device__ __align__(16) char  g_hT[(NB/KC)*HT_CHUNK]; // bf16 [chunk][ch][72]
__device__ __align__(16) float g_part[(size_t)NCHUNK*NB*CH];

// ---------------- math helpers ----------
__device__ __forceinline__ float ex2f(float x){
    float y; asm("ex2.approx.f32 %0, %1;" : "=f"(y) : "f"(x)); return y;
}
__device__ __forceinline__ float rcp_acc(float x){
    float r; asm("rcp.approx.f32 %0, %1;" : "=f"(r) : "f"(x));
    return r * fmaf(-x, r, 2.0f);
}
__device__ __forceinline__ float rsqrt_acc(float x){
    float r; asm("rsqrt.approx.f32 %0, %1;" : "=f"(r) : "f"(x));
    float e = x * r;
    return r * fmaf(-0.5f, e * r, 1.5f);
}
__device__ __forceinline__ float tanh_acc(float x){
    float ax = fabsf(x);
    float t  = ex2f(-2.8853900817779268f * ax);
    float y  = (1.0f - t) * rcp_acc(1.0f + t);
    return copysignf(y, x);
}

// CI = -log2(e)/(2*1.2^2)
#define CI_F   (-0.50093577808644655f)
#define M2CI_F ( 1.0018715561728931f)

__device__ __forceinline__ uint32_t smem_u32(const void* p){
    uint32_t a;
    asm("{ .reg .u64 t; cvta.to.shared.u64 t, %1; cvt.u32.u64 %0, t; }" : "=r"(a) : "l"(p));
    return a;
}
#define MMA16816(c0,c1,c2,c3,a0,a1,a2,a3,b0,b1) \
    asm volatile("mma.sync.aligned.m16n8k16.row.col.f32.bf16.bf16.f32 " \
        "{%0,%1,%2,%3}, {%4,%5,%6,%7}, {%8,%9}, {%0,%1,%2,%3};" \
        : "+f"(c0),"+f"(c1),"+f"(c2),"+f"(c3) \
        : "r"(a0),"r"(a1),"r"(a2),"r"(a3),"r"(b0),"r"(b1))
#define CVT_BF2(d,hi,lo) asm("cvt.rn.satfinite.bf16x2.f32 %0, %1, %2;" : "=r"(d) : "f"(hi), "f"(lo))

// ---- pm field (4 steps), 8 threads per row (2 centers each) ----
__device__ __forceinline__ void pm_oct(float zr[DL], const float* cs,
                                       const float* ms, int o)
{
    #pragma unroll
    for (int step=0; step<4; step++){
        float n = 0.f;
        float g[DL] = {0.f,0.f,0.f,0.f,0.f,0.f,0.f,0.f};
        #pragma unroll
        for (int cc=0;cc<2;cc++){
            int c = o*2 + cc;
            float rv[DL]; float r2 = 1e-4f;
            #pragma unroll
            for (int k=0;k<DL;k++){ rv[k] = zr[k]-cs[c*DL+k]; r2 = fmaf(rv[k],rv[k],r2); }
            float rinv = rsqrt_acc(r2);
            float mr = ms[c]*rinv;
            n += mr;
            float w = mr*rinv*rinv;
            #pragma unroll
            for (int k=0;k<DL;k++) g[k] = fmaf(-w, rv[k], g[k]);
        }
        #pragma unroll
        for (int off=1; off<8; off<<=1){
            n += __shfl_xor_sync(0xffffffffu, n, off);
            #pragma unroll
            for (int k=0;k<DL;k++) g[k] += __shfl_xor_sync(0xffffffffu, g[k], off);
        }
        float s = 0.15f * rcp_acc(n + 1.0f);
        #pragma unroll
        for (int k=0;k<DL;k++)
            zr[k] = fminf(fmaxf(fmaf(s, g[k], zr[k]), -3.f), 3.f);
    }
}

// ---- z side-products: g_z, g_sq(CI-scaled), g_zhl (hi/lo bf16) ----
__device__ __forceinline__ void z_store(const float zr[DL], int row)
{
    float s2 = 0.f;
    #pragma unroll
    for (int k=0;k<DL;k++) s2 = fmaf(zr[k], zr[k], s2);
    g_sq[row] = CI_F * s2;
    *(float4*)&g_z[row*DL]   = make_float4(zr[0],zr[1],zr[2],zr[3]);
    *(float4*)&g_z[row*DL+4] = make_float4(zr[4],zr[5],zr[6],zr[7]);
    __nv_bfloat16 hi[8], lo[8];
    #pragma unroll
    for (int k=0;k<DL;k++){
        hi[k] = __float2bfloat16(zr[k]);
        lo[k] = __float2bfloat16(zr[k] - __bfloat162float(hi[k]));
    }
    __nv_bfloat16* dst = &g_zhl[row*16];
    *(uint4*)dst       = *(uint4*)hi;
    *(uint4*)(dst + 8) = *(uint4*)lo;
}

// ---- hpre = 0.9*hc + 0.1*tanh(z@Wp+bp) for 4 channels; write g_hT (padded) ----
__device__ __forceinline__ void h_update4(const float zr[DL], const float* wps,
                                          const float* bps, int row, int c0,
                                          float4 hc)
{
    float a4[4];
    #pragma unroll
    for (int u=0;u<4;u++) a4[u] = bps[c0+u];
    #pragma unroll
    for (int k=0;k<DL;k++){
        float zk = zr[k];
        #pragma unroll
        for (int u=0;u<4;u++) a4[u] = fmaf(zk, wps[k*CH + c0 + u], a4[u]);
    }
    float4 hv;
    hv.x = fmaf(0.9f, hc.x, 0.1f*tanh_acc(a4[0]));
    hv.y = fmaf(0.9f, hc.y, 0.1f*tanh_acc(a4[1]));
    hv.z = fmaf(0.9f, hc.z, 0.1f*tanh_acc(a4[2]));
    hv.w = fmaf(0.9f, hc.w, 0.1f*tanh_acc(a4[3]));
    *(float4*)&g_hpre[(size_t)row*CH + c0] = hv;
    int jl = row & 63;
    char* base = g_hT + (size_t)(row >> 6) * HT_CHUNK + jl*2;
    *(__nv_bfloat16*)(base + (c0+0)*HT_ROW) = __float2bfloat16(hv.x);
    *(__nv_bfloat16*)(base + (c0+1)*HT_ROW) = __float2bfloat16(hv.y);
    *(__nv_bfloat16*)(base + (c0+2)*HT_ROW) = __float2bfloat16(hv.z);
    *(__nv_bfloat16*)(base + (c0+3)*HT_ROW) = __float2bfloat16(hv.w);
}

// ---------------- encoder + fused prep tail ----------------
__global__ __launch_bounds__(256) void enc_kernel(
    const float* __restrict__ x, const float* __restrict__ W1,
    const float* __restrict__ b1, const float* __restrict__ W2,
    const float* __restrict__ b2,
    const float* __restrict__ centers, const float* __restrict__ mus,
    const float* __restrict__ Wp, const float* __restrict__ bp)
{
    __shared__ float xs[32][33];
    __shared__ __align__(16) float ws[32][NH];
    __shared__ float hs[32][NH+1];
    __shared__ float w2s[NH*DL];
    __shared__ float cs[NC*DL];
    __shared__ float ms[NC];
    __shared__ float wps[DL*CH];
    __shared__ float bps[CH];

    const int tid = threadIdx.x;
    const int rowBase = blockIdx.x * 32;
    const int rg = tid >> 4;
    const int cg = tid & 15;

    for (int t = tid; t < NH*DL; t += 256) w2s[t] = W2[t];
    if (tid < NC*DL) cs[tid] = centers[tid];
    if (tid < NC) ms[tid] = mus[tid];
    if (tid < DL*CH) wps[tid] = Wp[tid];
    if (tid < CH) bps[tid] = bp[tid];

    float acc[2][8];
    #pragma unroll
    for (int a=0;a<2;a++)
        #pragma unroll
        for (int u=0;u<8;u++) acc[a][u]=0.f;

    for (int k0 = 0; k0 < DIN; k0 += 32) {
        for (int t = tid; t < 32*32; t += 256) {
            int r = t >> 5, k = t & 31;
            int kk = k0 + k;
            xs[r][k] = (kk < DIN) ? x[(size_t)(rowBase + r)*DIN + kk] : 0.f;
        }
        for (int t = tid; t < 32*NH; t += 256) {
            int k = t >> 7, c = t & (NH-1);
            int kk = k0 + k;
            ws[k][c] = (kk < DIN) ? W1[(size_t)kk*NH + c] : 0.f;
        }
        __syncthreads();
        #pragma unroll
        for (int kk = 0; kk < 32; kk++) {
            float x0 = xs[rg*2+0][kk];
            float x1 = xs[rg*2+1][kk];
            float4 w0 = *(const float4*)&ws[kk][cg*8];
            float4 w1 = *(const float4*)&ws[kk][cg*8+4];
            acc[0][0] = fmaf(x0, w0.x, acc[0][0]);
            acc[0][1] = fmaf(x0, w0.y, acc[0][1]);
            acc[0][2] = fmaf(x0, w0.z, acc[0][2]);
            acc[0][3] = fmaf(x0, w0.w, acc[0][3]);
            acc[0][4] = fmaf(x0, w1.x, acc[0][4]);
            acc[0][5] = fmaf(x0, w1.y, acc[0][5]);
            acc[0][6] = fmaf(x0, w1.z, acc[0][6]);
            acc[0][7] = fmaf(x0, w1.w, acc[0][7]);
            acc[1][0] = fmaf(x1, w0.x, acc[1][0]);
            acc[1][1] = fmaf(x1, w0.y, acc[1][1]);
            acc[1][2] = fmaf(x1, w0.z, acc[1][2]);
            acc[1][3] = fmaf(x1, w0.w, acc[1][3]);
            acc[1][4] = fmaf(x1, w1.x, acc[1][4]);
            acc[1][5] = fmaf(x1, w1.y, acc[1][5]);
            acc[1][6] = fmaf(x1, w1.z, acc[1][6]);
            acc[1][7] = fmaf(x1, w1.w, acc[1][7]);
        }
        __syncthreads();
    }
    #pragma unroll
    for (int a=0;a<2;a++){
        int r = rg*2+a;
        #pragma unroll
        for (int u=0;u<8;u++){
            int c = cg*8+u;
            hs[r][c] = tanh_acc(acc[a][u] + b1[c]);
        }
    }
    __syncthreads();
    {
        int r = tid >> 3;
        int o = tid & 7;
        float s = b2[o];
        #pragma unroll 16
        for (int k=0;k<NH;k++) s = fmaf(hs[r][k], w2s[k*DL+o], s);
        xs[r][o] = s;                  // stage z block-locally (reuse xs)
    }
    __syncthreads();

    // ---- fused prep tail: pm(z), side-products, hpre (h = 0) ----
    {
        const int r = tid >> 3;
        const int o = tid & 7;
        const int row = rowBase + r;
        float zr[DL];
        #pragma unroll
        for (int k=0;k<DL;k++) zr[k] = xs[r][k];
        pm_oct(zr, cs, ms, o);
        if (o == 0) z_store(zr, row);
        h_update4(zr, wps, bps, row, o*4, make_float4(0.f,0.f,0.f,0.f));
    }
}

// ---------- lateral: HMMA dot (hi/lo) -> K in regs -> HMMA K@H ----------
__global__ __launch_bounds__(256,3) void lateral_mma_kernel()
{
    __shared__ __align__(16) char zjs[KC*ZJ_ROW];      // 3 KB
    __shared__ __align__(16) float csq[KC];
    __shared__ __align__(16) char hTs[HT_CHUNK];       // 4.5 KB

    const int tid  = threadIdx.x;
    const int wid  = tid >> 5;
    const int lane = tid & 31;
    const int grp  = lane >> 2;
    const int t    = lane & 3;
    const int i0 = blockIdx.x * ITILE;
    const int jbase = blockIdx.y * JRANGE;

    const int rowa = i0 + wid*16 + grp;
    const int rowb = rowa + 8;
    uint32_t a0 = *(const uint32_t*)&g_zhl[rowa*16 + 2*t];
    uint32_t a1 = *(const uint32_t*)&g_zhl[rowb*16 + 2*t];
    uint32_t a2 = *(const uint32_t*)&g_zhl[rowa*16 + 8 + 2*t];
    uint32_t a3 = *(const uint32_t*)&g_zhl[rowb*16 + 8 + 2*t];
    const float csia = g_sq[rowa];
    const float csib = g_sq[rowb];

    const uint32_t zjB = smem_u32(zjs);
    const uint32_t hTB = smem_u32(hTs);

    float hacc[4][4];
    #pragma unroll
    for (int n=0;n<4;n++)
        #pragma unroll
        for (int r=0;r<4;r++) hacc[n][r] = 0.f;

    for (int c = 0; c < NCH; c++){
        const int j0g = jbase + c*KC;
        __syncthreads();
        // stage zj hi/lo (48B rows), csq, hT (144B rows)
        if (tid < 128){
            int j = tid >> 1, half = tid & 1;
            uint4 v = *(const uint4*)&g_zhl[(size_t)(j0g + j)*16 + half*8];
            *(uint4*)(zjs + j*ZJ_ROW + half*16) = v;
        }
        if (tid < KC) csq[tid] = g_sq[j0g + tid];
        {
            const uint4* src = (const uint4*)(g_hT + (size_t)(j0g >> 6) * HT_CHUNK);
            for (int s = tid; s < HT_CHUNK/16; s += 256) ((uint4*)hTs)[s] = src[s];
        }
        __syncthreads();

        #pragma unroll
        for (int ks = 0; ks < 4; ks++){
            uint32_t ka[4];
            #pragma unroll
            for (int g = 0; g < 2; g++){
                float cc0=0.f, cc1=0.f, cc2=0.f, cc3=0.f;
                int j = ks*16 + g*8 + grp;
                uint32_t b0, b1;
                asm volatile("ld.shared.b32 %0, [%1];" : "=r"(b0) : "r"(zjB + j*ZJ_ROW + 4*t));
                asm volatile("ld.shared.b32 %0, [%1];" : "=r"(b1) : "r"(zjB + j*ZJ_ROW + 16 + 4*t));
                MMA16816(cc0,cc1,cc2,cc3, a0,a1,a2,a3, b0,b1);   // hi.hi + lo.lo
                MMA16816(cc0,cc1,cc2,cc3, a0,a1,a2,a3, b1,b0);   // hi.lo + lo.hi
                float2 sj = *(const float2*)&csq[ks*16 + g*8 + 2*t];
                float ea0 = fmaf(M2CI_F, cc0, csia + sj.x);
                float ea1 = fmaf(M2CI_F, cc1, csia + sj.y);
                float ea2 = fmaf(M2CI_F, cc2, csib + sj.x);
                float ea3 = fmaf(M2CI_F, cc3, csib + sj.y);
                float e0 = ex2f(ea0), e1 = ex2f(ea1), e2 = ex2f(ea2), e3 = ex2f(ea3);
                float p0 = e0*e0, p1 = e1*e1, p2 = e2*e2, p3 = e3*e3;
                float K0 = fmaf(0.8f, p0*p0, -e0);
                float K1 = fmaf(0.8f, p1*p1, -e1);
                float K2 = fmaf(0.8f, p2*p2, -e2);
                float K3 = fmaf(0.8f, p3*p3, -e3);
                CVT_BF2(ka[g*2+0], K1, K0);   // row a: j-local (2t, 2t+1)
                CVT_BF2(ka[g*2+1], K3, K2);   // row b: j-local (2t, 2t+1)
            }
            // ka already in A-fragment order:
            //   ka[0]=rowa k0-7, ka[1]=rowb k0-7, ka[2]=rowa k8-15, ka[3]=rowb k8-15
            #pragma unroll
            for (int n = 0; n < 4; n++){
                uint32_t hb0, hb1;
                uint32_t haddr = hTB + (n*8 + grp)*HT_ROW + (ks*16 + 2*t)*2;
                asm volatile("ld.shared.b32 %0, [%1];" : "=r"(hb0) : "r"(haddr));
                asm volatile("ld.shared.b32 %0, [%1];" : "=r"(hb1) : "r"(haddr + 16));
                MMA16816(hacc[n][0],hacc[n][1],hacc[n][2],hacc[n][3],
                         ka[0],ka[1],ka[2],ka[3], hb0, hb1);
            }
        }
    }

    // epilogue
    {
        float* d0 = &g_part[((size_t)blockIdx.y*NB + rowa)*CH];
        float* d1 = &g_part[((size_t)blockIdx.y*NB + rowb)*CH];
        #pragma unroll
        for (int n = 0; n < 4; n++){
            *(float2*)&d0[n*8 + 2*t] = make_float2(hacc[n][0], hacc[n][1]);
            *(float2*)&d1[n*8 + 2*t] = make_float2(hacc[n][2], hacc[n][3]);
        }
    }
}

// ------- fused: hcomb = hpre + 0.05*sum(part); z = pm(z); h/hT update -------
__global__ __launch_bounds__(256) void fused_kernel(
    const float* __restrict__ centers, const float* __restrict__ mus,
    const float* __restrict__ Wp, const float* __restrict__ bp)
{
    __shared__ float cs[NC*DL];
    __shared__ float ms[NC];
    __shared__ float wps[DL*CH];
    __shared__ float bps[CH];
    const int tid = threadIdx.x;
    if (tid < NC*DL) cs[tid] = centers[tid];
    if (tid < NC) ms[tid] = mus[tid];
    if (tid < DL*CH) wps[tid] = Wp[tid];
    if (tid < CH) bps[tid] = bp[tid];
    __syncthreads();

    const int row = blockIdx.x*32 + (tid >> 3);
    const int o   = tid & 7;
    const int c0  = o*4;

    float tx=0.f, ty=0.f, tz=0.f, tw=0.f;
    #pragma unroll
    for (int c=0;c<NCHUNK;c++){
        float4 p = *(const float4*)&g_part[((size_t)c*NB + row)*CH + c0];
        tx+=p.x; ty+=p.y; tz+=p.z; tw+=p.w;
    }
    float4 h0 = *(const float4*)&g_hpre[(size_t)row*CH + c0];
    float4 hc;
    hc.x = fmaf(0.05f, tx, h0.x);
    hc.y = fmaf(0.05f, ty, h0.y);
    hc.z = fmaf(0.05f, tz, h0.z);
    hc.w = fmaf(0.05f, tw, h0.w);

    float zr[DL];
    {
        float4 a = *(const float4*)&g_z[row*DL];
        float4 b = *(const float4*)&g_z[row*DL+4];
        zr[0]=a.x; zr[1]=a.y; zr[2]=a.z; zr[3]=a.w;
        zr[4]=b.x; zr[5]=b.y; zr[6]=b.z; zr[7]=b.w;
    }
    pm_oct(zr, cs, ms, o);
    if (o == 0) z_store(zr, row);
    h_update4(zr, wps, bps, row, c0, hc);
}

// ------- final: hcomb = hpre + 0.05*sum(part); y = hcomb @ Wr + br -------
__global__ __launch_bounds__(128) void final_kernel(
    const float* __restrict__ Wr, const float* __restrict__ br,
    float* __restrict__ y)
{
    __shared__ float wrs[CH*DOUT];
    __shared__ float brs[DOUT];
    const int tid = threadIdx.x;
    for (int t=tid; t<CH*DOUT; t+=128) wrs[t] = Wr[t];
    if (tid < DOUT) brs[tid] = br[tid];
    __syncthreads();

    const int row = blockIdx.x*32 + (tid >> 2);
    const int q   = tid & 3;
    const int c0  = q*8;

    float t0x=0.f,t0y=0.f,t0z=0.f,t0w=0.f, t1x=0.f,t1y=0.f,t1z=0.f,t1w=0.f;
    #pragma unroll
    for (int c=0;c<NCHUNK;c++){
        const float* base = &g_part[((size_t)c*NB + row)*CH + c0];
        float4 p0 = *(const float4*)base;
        float4 p1 = *(const float4*)(base+4);
        t0x+=p0.x; t0y+=p0.y; t0z+=p0.z; t0w+=p0.w;
        t1x+=p1.x; t1y+=p1.y; t1z+=p1.z; t1w+=p1.w;
    }
    float4 h0 = *(const float4*)&g_hpre[(size_t)row*CH + c0];
    float4 h1 = *(const float4*)&g_hpre[(size_t)row*CH + c0 + 4];
    float hc[8];
    hc[0] = fmaf(0.05f, t0x, h0.x); hc[1] = fmaf(0.05f, t0y, h0.y);
    hc[2] = fmaf(0.05f, t0z, h0.z); hc[3] = fmaf(0.05f, t0w, h0.w);
    hc[4] = fmaf(0.05f, t1x, h1.x); hc[5] = fmaf(0.05f, t1y, h1.y);
    hc[6] = fmaf(0.05f, t1z, h1.z); hc[7] = fmaf(0.05f, t1w, h1.w);

    float o[DOUT];
    #pragma unroll
    for (int d=0; d<DOUT; d++) o[d] = 0.f;
    #pragma unroll
    for (int u=0;u<8;u++){
        float hcu = hc[u];
        #pragma unroll
        for (int d=0; d<DOUT; d++) o[d] = fmaf(hcu, wrs[(c0+u)*DOUT+d], o[d]);
    }
    #pragma unroll
    for (int off=1; off<4; off<<=1){
        #pragma unroll
        for (int d=0; d<DOUT; d++) o[d] += __shfl_xor_sync(0xffffffffu, o[d], off);
    }
    if (q == 0){
        #pragma unroll
        for (int d=0; d<DOUT; d++) y[(size_t)row*DOUT + d] = o[d] + brs[d];
    }
}

// ---------------- launch ----------------
extern "C" void kernel_launch(void* const* d_in, const int* in_sizes, int n_in,
                              void* d_out, int out_size)
{
    const float* x       = (const float*)d_in[0];
    const float* W1      = (const float*)d_in[1];
    const float* b1      = (const float*)d_in[2];
    const float* W2      = (const float*)d_in[3];
    const float* b2      = (const float*)d_in[4];
    const float* centers = (const float*)d_in[5];
    const float* mus     = (const float*)d_in[6];
    const float* Wp      = (const float*)d_in[7];
    const float* bp      = (const float*)d_in[8];
    const float* Wr      = (const float*)d_in[9];
    const float* br      = (const float*)d_in[10];
    float* y = (float*)d_out;

    enc_kernel<<<NB/32, 256>>>(x, W1, b1, W2, b2, centers, mus, Wp, bp);
    for (int t = 1; t <= TSTEPS; t++){
        lateral_mma_kernel<<<dim3(NB/ITILE, NJS), 256>>>();
        if (t < TSTEPS)
            fused_kernel<<<NB/32, 256>>>(centers, mus, Wp, bp);
    }
    final_kernel<<<NB/32, 128>>>(Wr, br, y);
}

// round 10
// speedup vs baseline: 1.9688x; 1.0106x over previous
#include <cuda_runtime.h>
#include <cuda_bf16.h>
#include <cstdint>

#define NB   4096
#define DIN  784
#define NH   128
#define DL   8
#define NC   16
#define CH   32
#define DOUT 10
#define NCHUNK 16
#define TSTEPS 5

// lateral tiling
#define ITILE 128
#define KC    64
#define NJS   16
#define JRANGE (NB/NJS)     // 256
#define NCH   (JRANGE/KC)   // 4

#define HT_ROW 144              // 72 bf16 per hT row (padded, conflict-free LDS)
#define HT_CHUNK (CH*HT_ROW)    // 4608 B per 64-j chunk
#define ZJ_ROW 48               // 24 bf16 per zj row (16 used)

// ---------------- scratch ----------------
__device__ __align__(16) float g_z[NB*DL];
__device__ float g_sq[NB];                       // CI * |z|^2
__device__ __align__(16) __nv_bfloat16 g_zhl[NB*16];   // [hi0..hi7, lo0..lo7]
__device__ __align__(16) float g_hpre[NB*CH];
__device__ __align__(16) char  g_hT[(NB/KC)*HT_CHUNK]; // bf16 [chunk][ch][72]
__device__ __align__(16) float g_part[(size_t)NCHUNK*NB*CH];

// ---------------- math helpers ----------
__device__ __forceinline__ float ex2f(float x){
    float y; asm("ex2.approx.f32 %0, %1;" : "=f"(y) : "f"(x)); return y;
}
__device__ __forceinline__ float rcp_acc(float x){
    float r; asm("rcp.approx.f32 %0, %1;" : "=f"(r) : "f"(x));
    return r * fmaf(-x, r, 2.0f);
}
__device__ __forceinline__ float rsqrt_acc(float x){
    float r; asm("rsqrt.approx.f32 %0, %1;" : "=f"(r) : "f"(x));
    float e = x * r;
    return r * fmaf(-0.5f, e * r, 1.5f);
}
__device__ __forceinline__ float tanh_acc(float x){
    float ax = fabsf(x);
    float t  = ex2f(-2.8853900817779268f * ax);
    float y  = (1.0f - t) * rcp_acc(1.0f + t);
    return copysignf(y, x);
}

// CI = -log2(e)/(2*1.2^2)
#define CI_F   (-0.50093577808644655f)
#define M2CI_F ( 1.0018715561728931f)

__device__ __forceinline__ uint32_t smem_u32(const void* p){
    uint32_t a;
    asm("{ .reg .u64 t; cvta.to.shared.u64 t, %1; cvt.u32.u64 %0, t; }" : "=r"(a) : "l"(p));
    return a;
}
#define MMA16816(c0,c1,c2,c3,a0,a1,a2,a3,b0,b1) \
    asm volatile("mma.sync.aligned.m16n8k16.row.col.f32.bf16.bf16.f32 " \
        "{%0,%1,%2,%3}, {%4,%5,%6,%7}, {%8,%9}, {%0,%1,%2,%3};" \
        : "+f"(c0),"+f"(c1),"+f"(c2),"+f"(c3) \
        : "r"(a0),"r"(a1),"r"(a2),"r"(a3),"r"(b0),"r"(b1))
#define CVT_BF2(d,hi,lo) asm("cvt.rn.satfinite.bf16x2.f32 %0, %1, %2;" : "=r"(d) : "f"(hi), "f"(lo))

// ---- pm field (4 steps), 8 threads per row (2 centers each) ----
__device__ __forceinline__ void pm_oct(float zr[DL], const float* cs,
                                       const float* ms, int o)
{
    #pragma unroll
    for (int step=0; step<4; step++){
        float n = 0.f;
        float g[DL] = {0.f,0.f,0.f,0.f,0.f,0.f,0.f,0.f};
        #pragma unroll
        for (int cc=0;cc<2;cc++){
            int c = o*2 + cc;
            float rv[DL]; float r2 = 1e-4f;
            #pragma unroll
            for (int k=0;k<DL;k++){ rv[k] = zr[k]-cs[c*DL+k]; r2 = fmaf(rv[k],rv[k],r2); }
            float rinv = rsqrt_acc(r2);
            float mr = ms[c]*rinv;
            n += mr;
            float w = mr*rinv*rinv;
            #pragma unroll
            for (int k=0;k<DL;k++) g[k] = fmaf(-w, rv[k], g[k]);
        }
        #pragma unroll
        for (int off=1; off<8; off<<=1){
            n += __shfl_xor_sync(0xffffffffu, n, off);
            #pragma unroll
            for (int k=0;k<DL;k++) g[k] += __shfl_xor_sync(0xffffffffu, g[k], off);
        }
        float s = 0.15f * rcp_acc(n + 1.0f);
        #pragma unroll
        for (int k=0;k<DL;k++)
            zr[k] = fminf(fmaxf(fmaf(s, g[k], zr[k]), -3.f), 3.f);
    }
}

// ---- z side-products: g_z, g_sq(CI-scaled), g_zhl (hi/lo bf16) ----
__device__ __forceinline__ void z_store(const float zr[DL], int row)
{
    float s2 = 0.f;
    #pragma unroll
    for (int k=0;k<DL;k++) s2 = fmaf(zr[k], zr[k], s2);
    g_sq[row] = CI_F * s2;
    *(float4*)&g_z[row*DL]   = make_float4(zr[0],zr[1],zr[2],zr[3]);
    *(float4*)&g_z[row*DL+4] = make_float4(zr[4],zr[5],zr[6],zr[7]);
    __nv_bfloat16 hi[8], lo[8];
    #pragma unroll
    for (int k=0;k<DL;k++){
        hi[k] = __float2bfloat16(zr[k]);
        lo[k] = __float2bfloat16(zr[k] - __bfloat162float(hi[k]));
    }
    __nv_bfloat16* dst = &g_zhl[row*16];
    *(uint4*)dst       = *(uint4*)hi;
    *(uint4*)(dst + 8) = *(uint4*)lo;
}

// ---- hpre = 0.9*hc + 0.1*tanh(z@Wp+bp) for 4 channels; write g_hT (padded) ----
__device__ __forceinline__ void h_update4(const float zr[DL], const float* wps,
                                          const float* bps, int row, int c0,
                                          float4 hc)
{
    float a4[4];
    #pragma unroll
    for (int u=0;u<4;u++) a4[u] = bps[c0+u];
    #pragma unroll
    for (int k=0;k<DL;k++){
        float zk = zr[k];
        #pragma unroll
        for (int u=0;u<4;u++) a4[u] = fmaf(zk, wps[k*CH + c0 + u], a4[u]);
    }
    float4 hv;
    hv.x = fmaf(0.9f, hc.x, 0.1f*tanh_acc(a4[0]));
    hv.y = fmaf(0.9f, hc.y, 0.1f*tanh_acc(a4[1]));
    hv.z = fmaf(0.9f, hc.z, 0.1f*tanh_acc(a4[2]));
    hv.w = fmaf(0.9f, hc.w, 0.1f*tanh_acc(a4[3]));
    *(float4*)&g_hpre[(size_t)row*CH + c0] = hv;
    int jl = row & 63;
    char* base = g_hT + (size_t)(row >> 6) * HT_CHUNK + jl*2;
    *(__nv_bfloat16*)(base + (c0+0)*HT_ROW) = __float2bfloat16(hv.x);
    *(__nv_bfloat16*)(base + (c0+1)*HT_ROW) = __float2bfloat16(hv.y);
    *(__nv_bfloat16*)(base + (c0+2)*HT_ROW) = __float2bfloat16(hv.z);
    *(__nv_bfloat16*)(base + (c0+3)*HT_ROW) = __float2bfloat16(hv.w);
}

// ---------------- encoder + fused prep tail ----------------
__global__ __launch_bounds__(256) void enc_kernel(
    const float* __restrict__ x, const float* __restrict__ W1,
    const float* __restrict__ b1, const float* __restrict__ W2,
    const float* __restrict__ b2,
    const float* __restrict__ centers, const float* __restrict__ mus,
    const float* __restrict__ Wp, const float* __restrict__ bp)
{
    __shared__ float xs[32][33];
    __shared__ __align__(16) float ws[32][NH];
    __shared__ float hs[32][NH+1];
    __shared__ float w2s[NH*DL];
    __shared__ float cs[NC*DL];
    __shared__ float ms[NC];
    __shared__ float wps[DL*CH];
    __shared__ float bps[CH];

    const int tid = threadIdx.x;
    const int rowBase = blockIdx.x * 32;
    const int rg = tid >> 4;
    const int cg = tid & 15;

    for (int t = tid; t < NH*DL; t += 256) w2s[t] = W2[t];
    if (tid < NC*DL) cs[tid] = centers[tid];
    if (tid < NC) ms[tid] = mus[tid];
    if (tid < DL*CH) wps[tid] = Wp[tid];
    if (tid < CH) bps[tid] = bp[tid];

    float acc[2][8];
    #pragma unroll
    for (int a=0;a<2;a++)
        #pragma unroll
        for (int u=0;u<8;u++) acc[a][u]=0.f;

    for (int k0 = 0; k0 < DIN; k0 += 32) {
        for (int t = tid; t < 32*32; t += 256) {
            int r = t >> 5, k = t & 31;
            int kk = k0 + k;
            xs[r][k] = (kk < DIN) ? x[(size_t)(rowBase + r)*DIN + kk] : 0.f;
        }
        for (int t = tid; t < 32*NH; t += 256) {
            int k = t >> 7, c = t & (NH-1);
            int kk = k0 + k;
            ws[k][c] = (kk < DIN) ? W1[(size_t)kk*NH + c] : 0.f;
        }
        __syncthreads();
        #pragma unroll
        for (int kk = 0; kk < 32; kk++) {
            float x0 = xs[rg*2+0][kk];
            float x1 = xs[rg*2+1][kk];
            float4 w0 = *(const float4*)&ws[kk][cg*8];
            float4 w1 = *(const float4*)&ws[kk][cg*8+4];
            acc[0][0] = fmaf(x0, w0.x, acc[0][0]);
            acc[0][1] = fmaf(x0, w0.y, acc[0][1]);
            acc[0][2] = fmaf(x0, w0.z, acc[0][2]);
            acc[0][3] = fmaf(x0, w0.w, acc[0][3]);
            acc[0][4] = fmaf(x0, w1.x, acc[0][4]);
            acc[0][5] = fmaf(x0, w1.y, acc[0][5]);
            acc[0][6] = fmaf(x0, w1.z, acc[0][6]);
            acc[0][7] = fmaf(x0, w1.w, acc[0][7]);
            acc[1][0] = fmaf(x1, w0.x, acc[1][0]);
            acc[1][1] = fmaf(x1, w0.y, acc[1][1]);
            acc[1][2] = fmaf(x1, w0.z, acc[1][2]);
            acc[1][3] = fmaf(x1, w0.w, acc[1][3]);
            acc[1][4] = fmaf(x1, w1.x, acc[1][4]);
            acc[1][5] = fmaf(x1, w1.y, acc[1][5]);
            acc[1][6] = fmaf(x1, w1.z, acc[1][6]);
            acc[1][7] = fmaf(x1, w1.w, acc[1][7]);
        }
        __syncthreads();
    }
    #pragma unroll
    for (int a=0;a<2;a++){
        int r = rg*2+a;
        #pragma unroll
        for (int u=0;u<8;u++){
            int c = cg*8+u;
            hs[r][c] = tanh_acc(acc[a][u] + b1[c]);
        }
    }
    __syncthreads();
    {
        int r = tid >> 3;
        int o = tid & 7;
        float s = b2[o];
        #pragma unroll 16
        for (int k=0;k<NH;k++) s = fmaf(hs[r][k], w2s[k*DL+o], s);
        xs[r][o] = s;                  // stage z block-locally (reuse xs)
    }
    __syncthreads();

    // ---- fused prep tail: pm(z), side-products, hpre (h = 0) ----
    {
        const int r = tid >> 3;
        const int o = tid & 7;
        const int row = rowBase + r;
        float zr[DL];
        #pragma unroll
        for (int k=0;k<DL;k++) zr[k] = xs[r][k];
        pm_oct(zr, cs, ms, o);
        if (o == 0) z_store(zr, row);
        h_update4(zr, wps, bps, row, o*4, make_float4(0.f,0.f,0.f,0.f));
    }
}

// ---------- lateral: HMMA dot (hi/lo) -> K in regs -> HMMA K@H ----------
__global__ __launch_bounds__(256,4) void lateral_mma_kernel()
{
    __shared__ __align__(16) char zjs[KC*ZJ_ROW];      // 3 KB
    __shared__ __align__(16) float csq[KC];
    __shared__ __align__(16) char hTs[HT_CHUNK];       // 4.5 KB

    const int tid  = threadIdx.x;
    const int wid  = tid >> 5;
    const int lane = tid & 31;
    const int grp  = lane >> 2;
    const int t    = lane & 3;
    const int i0 = blockIdx.x * ITILE;
    const int jbase = blockIdx.y * JRANGE;

    const int rowa = i0 + wid*16 + grp;
    const int rowb = rowa + 8;
    uint32_t a0 = *(const uint32_t*)&g_zhl[rowa*16 + 2*t];
    uint32_t a1 = *(const uint32_t*)&g_zhl[rowb*16 + 2*t];
    uint32_t a2 = *(const uint32_t*)&g_zhl[rowa*16 + 8 + 2*t];
    uint32_t a3 = *(const uint32_t*)&g_zhl[rowb*16 + 8 + 2*t];
    const float csia = g_sq[rowa];
    const float csib = g_sq[rowb];

    const uint32_t zjB = smem_u32(zjs);
    const uint32_t hTB = smem_u32(hTs);

    float hacc[4][4];
    #pragma unroll
    for (int n=0;n<4;n++)
        #pragma unroll
        for (int r=0;r<4;r++) hacc[n][r] = 0.f;

    for (int c = 0; c < NCH; c++){
        const int j0g = jbase + c*KC;
        __syncthreads();
        // stage zj hi/lo (48B rows), csq, hT (144B rows)
        if (tid < 128){
            int j = tid >> 1, half = tid & 1;
            uint4 v = *(const uint4*)&g_zhl[(size_t)(j0g + j)*16 + half*8];
            *(uint4*)(zjs + j*ZJ_ROW + half*16) = v;
        }
        if (tid < KC) csq[tid] = g_sq[j0g + tid];
        {
            const uint4* src = (const uint4*)(g_hT + (size_t)(j0g >> 6) * HT_CHUNK);
            for (int s = tid; s < HT_CHUNK/16; s += 256) ((uint4*)hTs)[s] = src[s];
        }
        __syncthreads();

        #pragma unroll
        for (int ks = 0; ks < 4; ks++){
            uint32_t ka[4];
            #pragma unroll
            for (int g = 0; g < 2; g++){
                float cc0=0.f, cc1=0.f, cc2=0.f, cc3=0.f;
                int j = ks*16 + g*8 + grp;
                uint32_t b0, b1;
                asm volatile("ld.shared.b32 %0, [%1];" : "=r"(b0) : "r"(zjB + j*ZJ_ROW + 4*t));
                asm volatile("ld.shared.b32 %0, [%1];" : "=r"(b1) : "r"(zjB + j*ZJ_ROW + 16 + 4*t));
                MMA16816(cc0,cc1,cc2,cc3, a0,a1,a2,a3, b0,b1);   // hi.hi + lo.lo
                MMA16816(cc0,cc1,cc2,cc3, a0,a1,a2,a3, b1,b0);   // hi.lo + lo.hi
                float2 sj = *(const float2*)&csq[ks*16 + g*8 + 2*t];
                float ea0 = fmaf(M2CI_F, cc0, csia + sj.x);
                float ea1 = fmaf(M2CI_F, cc1, csia + sj.y);
                float ea2 = fmaf(M2CI_F, cc2, csib + sj.x);
                float ea3 = fmaf(M2CI_F, cc3, csib + sj.y);
                float e0 = ex2f(ea0), e1 = ex2f(ea1), e2 = ex2f(ea2), e3 = ex2f(ea3);
                float p0 = e0*e0, p1 = e1*e1, p2 = e2*e2, p3 = e3*e3;
                float K0 = fmaf(0.8f, p0*p0, -e0);
                float K1 = fmaf(0.8f, p1*p1, -e1);
                float K2 = fmaf(0.8f, p2*p2, -e2);
                float K3 = fmaf(0.8f, p3*p3, -e3);
                CVT_BF2(ka[g*2+0], K1, K0);   // row a: j-local (2t, 2t+1)
                CVT_BF2(ka[g*2+1], K3, K2);   // row b: j-local (2t, 2t+1)
            }
            // ka already in A-fragment order:
            //   ka[0]=rowa k0-7, ka[1]=rowb k0-7, ka[2]=rowa k8-15, ka[3]=rowb k8-15
            #pragma unroll
            for (int n = 0; n < 4; n++){
                uint32_t hb0, hb1;
                uint32_t haddr = hTB + (n*8 + grp)*HT_ROW + (ks*16 + 2*t)*2;
                asm volatile("ld.shared.b32 %0, [%1];" : "=r"(hb0) : "r"(haddr));
                asm volatile("ld.shared.b32 %0, [%1];" : "=r"(hb1) : "r"(haddr + 16));
                MMA16816(hacc[n][0],hacc[n][1],hacc[n][2],hacc[n][3],
                         ka[0],ka[1],ka[2],ka[3], hb0, hb1);
            }
        }
    }

    // epilogue
    {
        float* d0 = &g_part[((size_t)blockIdx.y*NB + rowa)*CH];
        float* d1 = &g_part[((size_t)blockIdx.y*NB + rowb)*CH];
        #pragma unroll
        for (int n = 0; n < 4; n++){
            *(float2*)&d0[n*8 + 2*t] = make_float2(hacc[n][0], hacc[n][1]);
            *(float2*)&d1[n*8 + 2*t] = make_float2(hacc[n][2], hacc[n][3]);
        }
    }
}

// ------- fused: hcomb = hpre + 0.05*sum(part); z = pm(z); h/hT update -------
__global__ __launch_bounds__(128) void fused_kernel(
    const float* __restrict__ centers, const float* __restrict__ mus,
    const float* __restrict__ Wp, const float* __restrict__ bp)
{
    __shared__ float cs[NC*DL];
    __shared__ float ms[NC];
    __shared__ float wps[DL*CH];
    __shared__ float bps[CH];
    const int tid = threadIdx.x;
    if (tid < NC*DL) cs[tid] = centers[tid];
    if (tid < NC) ms[tid] = mus[tid];
    for (int t = tid; t < DL*CH; t += 128) wps[t] = Wp[t];
    if (tid < CH) bps[tid] = bp[tid];
    __syncthreads();

    const int row = blockIdx.x*16 + (tid >> 3);
    const int o   = tid & 7;
    const int c0  = o*4;

    float tx=0.f, ty=0.f, tz=0.f, tw=0.f;
    #pragma unroll
    for (int c=0;c<NCHUNK;c++){
        float4 p = *(const float4*)&g_part[((size_t)c*NB + row)*CH + c0];
        tx+=p.x; ty+=p.y; tz+=p.z; tw+=p.w;
    }
    float4 h0 = *(const float4*)&g_hpre[(size_t)row*CH + c0];
    float4 hc;
    hc.x = fmaf(0.05f, tx, h0.x);
    hc.y = fmaf(0.05f, ty, h0.y);
    hc.z = fmaf(0.05f, tz, h0.z);
    hc.w = fmaf(0.05f, tw, h0.w);

    float zr[DL];
    {
        float4 a = *(const float4*)&g_z[row*DL];
        float4 b = *(const float4*)&g_z[row*DL+4];
        zr[0]=a.x; zr[1]=a.y; zr[2]=a.z; zr[3]=a.w;
        zr[4]=b.x; zr[5]=b.y; zr[6]=b.z; zr[7]=b.w;
    }
    pm_oct(zr, cs, ms, o);
    if (o == 0) z_store(zr, row);
    h_update4(zr, wps, bps, row, c0, hc);
}

// ------- final: hcomb = hpre + 0.05*sum(part); y = hcomb @ Wr + br -------
__global__ __launch_bounds__(128) void final_kernel(
    const float* __restrict__ Wr, const float* __restrict__ br,
    float* __restrict__ y)
{
    __shared__ float wrs[CH*DOUT];
    __shared__ float brs[DOUT];
    const int tid = threadIdx.x;
    for (int t=tid; t<CH*DOUT; t+=128) wrs[t] = Wr[t];
    if (tid < DOUT) brs[tid] = br[tid];
    __syncthreads();

    const int row = blockIdx.x*32 + (tid >> 2);
    const int q   = tid & 3;
    const int c0  = q*8;

    float t0x=0.f,t0y=0.f,t0z=0.f,t0w=0.f, t1x=0.f,t1y=0.f,t1z=0.f,t1w=0.f;
    #pragma unroll
    for (int c=0;c<NCHUNK;c++){
        const float* base = &g_part[((size_t)c*NB + row)*CH + c0];
        float4 p0 = *(const float4*)base;
        float4 p1 = *(const float4*)(base+4);
        t0x+=p0.x; t0y+=p0.y; t0z+=p0.z; t0w+=p0.w;
        t1x+=p1.x; t1y+=p1.y; t1z+=p1.z; t1w+=p1.w;
    }
    float4 h0 = *(const float4*)&g_hpre[(size_t)row*CH + c0];
    float4 h1 = *(const float4*)&g_hpre[(size_t)row*CH + c0 + 4];
    float hc[8];
    hc[0] = fmaf(0.05f, t0x, h0.x); hc[1] = fmaf(0.05f, t0y, h0.y);
    hc[2] = fmaf(0.05f, t0z, h0.z); hc[3] = fmaf(0.05f, t0w, h0.w);
    hc[4] = fmaf(0.05f, t1x, h1.x); hc[5] = fmaf(0.05f, t1y, h1.y);
    hc[6] = fmaf(0.05f, t1z, h1.z); hc[7] = fmaf(0.05f, t1w, h1.w);

    float o[DOUT];
    #pragma unroll
    for (int d=0; d<DOUT; d++) o[d] = 0.f;
    #pragma unroll
    for (int u=0;u<8;u++){
        float hcu = hc[u];
        #pragma unroll
        for (int d=0; d<DOUT; d++) o[d] = fmaf(hcu, wrs[(c0+u)*DOUT+d], o[d]);
    }
    #pragma unroll
    for (int off=1; off<4; off<<=1){
        #pragma unroll
        for (int d=0; d<DOUT; d++) o[d] += __shfl_xor_sync(0xffffffffu, o[d], off);
    }
    if (q == 0){
        #pragma unroll
        for (int d=0; d<DOUT; d++) y[(size_t)row*DOUT + d] = o[d] + brs[d];
    }
}

// ---------------- launch ----------------
extern "C" void kernel_launch(void* const* d_in, const int* in_sizes, int n_in,
                              void* d_out, int out_size)
{
    const float* x       = (const float*)d_in[0];
    const float* W1      = (const float*)d_in[1];
    const float* b1      = (const float*)d_in[2];
    const float* W2      = (const float*)d_in[3];
    const float* b2      = (const float*)d_in[4];
    const float* centers = (const float*)d_in[5];
    const float* mus     = (const float*)d_in[6];
    const float* Wp      = (const float*)d_in[7];
    const float* bp      = (const float*)d_in[8];
    const float* Wr      = (const float*)d_in[9];
    const float* br      = (const float*)d_in[10];
    float* y = (float*)d_out;

    enc_kernel<<<NB/32, 256>>>(x, W1, b1, W2, b2, centers, mus, Wp, bp);
    for (int t = 1; t <= TSTEPS; t++){
        lateral_mma_kernel<<<dim3(NB/ITILE, NJS), 256>>>();
        if (t < TSTEPS)
            fused_kernel<<<NB/16, 128>>>(centers, mus, Wp, bp);
    }
    final_kernel<<<NB/32, 128>>>(Wr, br, y);
}